// round 1
// baseline (speedup 1.0000x reference)
#include <cuda_runtime.h>
#include <cuda_bf16.h>
#include <math.h>

// ---------------- problem dims ----------------
#define BATCH 4
#define SEQ   2048
#define EMB   1024
#define NHEAD 16
#define HSZ   64            // EMB / NHEAD
#define MTOT  (BATCH * SEQ) // 8192

// ---------------- scratch (device globals; no runtime allocation) ----------
// q/k/v in [B, H, T, HS] layout; y in [B, T, C] layout
__device__ __align__(128) float g_q[(size_t)BATCH * NHEAD * SEQ * HSZ];
__device__ __align__(128) float g_k[(size_t)BATCH * NHEAD * SEQ * HSZ];
__device__ __align__(128) float g_v[(size_t)BATCH * NHEAD * SEQ * HSZ];
__device__ __align__(128) float g_y[(size_t)MTOT * EMB];

// ---------------- SGEMM tile config ----------------
#define BM 128
#define BN 128
#define BK 8

// =============================================================
// Kernel 1: QKV projection.  out = X @ W + b, scattered to [B,H,T,HS].
// blockIdx.z selects which of q/k/v.
// =============================================================
__global__ __launch_bounds__(256) void qkv_kernel(
    const float* __restrict__ X,
    const float* __restrict__ W0, const float* __restrict__ W1, const float* __restrict__ W2,
    const float* __restrict__ b0, const float* __restrict__ b1, const float* __restrict__ b2)
{
    const int mat = blockIdx.z;
    const float* W    = (mat == 0) ? W0 : (mat == 1) ? W1 : W2;
    const float* bias = (mat == 0) ? b0 : (mat == 1) ? b1 : b2;
    float* dst        = (mat == 0) ? g_q : (mat == 1) ? g_k : g_v;

    __shared__ __align__(16) float As[BK][BM];
    __shared__ __align__(16) float Bs[BK][BN];

    const int tid = threadIdx.x;
    const int m0 = blockIdx.y * BM;
    const int n0 = blockIdx.x * BN;

    // global->smem load mapping
    const int arow = tid >> 1;          // 0..127
    const int acol = (tid & 1) * 4;     // 0 or 4
    const int brow = tid >> 5;          // 0..7
    const int bcol = (tid & 31) * 4;    // 0..124

    const int ty = tid >> 4;            // 0..15
    const int tx = tid & 15;            // 0..15

    float acc[8][8];
    #pragma unroll
    for (int i = 0; i < 8; i++)
        #pragma unroll
        for (int j = 0; j < 8; j++) acc[i][j] = 0.f;

    for (int k0 = 0; k0 < EMB; k0 += BK) {
        float4 av = *(const float4*)(X + (size_t)(m0 + arow) * EMB + k0 + acol);
        float4 bv = *(const float4*)(W + (size_t)(k0 + brow) * EMB + n0 + bcol);
        As[acol + 0][arow] = av.x;
        As[acol + 1][arow] = av.y;
        As[acol + 2][arow] = av.z;
        As[acol + 3][arow] = av.w;
        *(float4*)&Bs[brow][bcol] = bv;
        __syncthreads();

        #pragma unroll
        for (int k = 0; k < BK; k++) {
            float a[8], b[8];
            *(float4*)(a)     = *(const float4*)&As[k][ty * 4];
            *(float4*)(a + 4) = *(const float4*)&As[k][64 + ty * 4];
            *(float4*)(b)     = *(const float4*)&Bs[k][tx * 4];
            *(float4*)(b + 4) = *(const float4*)&Bs[k][64 + tx * 4];
            #pragma unroll
            for (int i = 0; i < 8; i++)
                #pragma unroll
                for (int j = 0; j < 8; j++) acc[i][j] += a[i] * b[j];
        }
        __syncthreads();
    }

    // epilogue: add bias, scatter to [B, H, T, HS]
    #pragma unroll
    for (int i = 0; i < 8; i++) {
        const int rr = ((i < 4) ? (ty * 4 + i) : (64 + ty * 4 + i - 4));
        const int m = m0 + rr;
        const int bidx = m >> 11;        // /SEQ
        const int t    = m & (SEQ - 1);
        #pragma unroll
        for (int j = 0; j < 8; j++) {
            const int cc = ((j < 4) ? (tx * 4 + j) : (64 + tx * 4 + j - 4));
            const int n = n0 + cc;
            const int h = n >> 6;        // /HSZ
            const int d = n & (HSZ - 1);
            const float v = acc[i][j] + bias[n];
            dst[((((size_t)bidx * NHEAD + h) * SEQ) + t) * HSZ + d] = v;
        }
    }
}

// =============================================================
// Kernel 2: causal flash attention.
// 1 thread = 1 query row. K/V tiles of 32 keys in smem (broadcast reads).
// grid: (SEQ/128, BATCH*NHEAD), block: 128 threads.
// =============================================================
#define FM 128  // queries per block
#define FN 32   // keys per tile

__global__ __launch_bounds__(128) void attn_kernel()
{
    const int bh  = blockIdx.y;                     // 0..63
    const int tq  = blockIdx.x * FM + threadIdx.x;  // query index in [0,SEQ)
    const size_t base = (size_t)bh * SEQ * HSZ;
    const float* Kp = g_k + base;
    const float* Vp = g_v + base;

    __shared__ __align__(16) float Ks[FN][HSZ];
    __shared__ __align__(16) float Vs[FN][HSZ];

    // q row in registers, pre-scaled by 1/sqrt(HS)
    float q[HSZ];
    {
        const float* Qp = g_q + base + (size_t)tq * HSZ;
        #pragma unroll
        for (int i = 0; i < HSZ / 4; i++) {
            float4 v4 = *(const float4*)(Qp + i * 4);
            q[i * 4 + 0] = v4.x * 0.125f;
            q[i * 4 + 1] = v4.y * 0.125f;
            q[i * 4 + 2] = v4.z * 0.125f;
            q[i * 4 + 3] = v4.w * 0.125f;
        }
    }

    float acc[HSZ];
    #pragma unroll
    for (int d = 0; d < HSZ; d++) acc[d] = 0.f;
    float mx = -1e30f, l = 0.f;

    const int kend = blockIdx.x * FM + FM;  // causal: keys < kend for this block
    for (int kb = 0; kb < kend; kb += FN) {
        __syncthreads();
        for (int i = threadIdx.x; i < FN * HSZ / 4; i += FM) {
            ((float4*)&Ks[0][0])[i] = *(const float4*)(Kp + (size_t)kb * HSZ + i * 4);
            ((float4*)&Vs[0][0])[i] = *(const float4*)(Vp + (size_t)kb * HSZ + i * 4);
        }
        __syncthreads();

        float s[FN];
        #pragma unroll 4
        for (int j = 0; j < FN; j++) {
            const float4* krow = (const float4*)Ks[j];
            float ss = 0.f;
            #pragma unroll
            for (int d4 = 0; d4 < HSZ / 4; d4++) {
                float4 kv = krow[d4];
                ss += q[d4 * 4 + 0] * kv.x;
                ss += q[d4 * 4 + 1] * kv.y;
                ss += q[d4 * 4 + 2] * kv.z;
                ss += q[d4 * 4 + 3] * kv.w;
            }
            s[j] = ((kb + j) <= tq) ? ss : -1e30f;
        }

        float mnew = mx;
        #pragma unroll
        for (int j = 0; j < FN; j++) mnew = fmaxf(mnew, s[j]);
        const float corr = __expf(mx - mnew);
        mx = mnew;

        float psum = 0.f;
        #pragma unroll
        for (int j = 0; j < FN; j++) {
            s[j] = __expf(s[j] - mnew);
            psum += s[j];
        }
        l = l * corr + psum;

        #pragma unroll
        for (int d = 0; d < HSZ; d++) acc[d] *= corr;

        #pragma unroll 4
        for (int j = 0; j < FN; j++) {
            const float p = s[j];
            const float4* vrow = (const float4*)Vs[j];
            #pragma unroll
            for (int d4 = 0; d4 < HSZ / 4; d4++) {
                float4 vv = vrow[d4];
                acc[d4 * 4 + 0] += p * vv.x;
                acc[d4 * 4 + 1] += p * vv.y;
                acc[d4 * 4 + 2] += p * vv.z;
                acc[d4 * 4 + 3] += p * vv.w;
            }
        }
    }

    const float inv = 1.f / l;
    const int bidx = bh / NHEAD;
    const int h    = bh % NHEAD;
    float* yp = g_y + ((size_t)bidx * SEQ + tq) * EMB + h * HSZ;
    #pragma unroll
    for (int i = 0; i < HSZ / 4; i++) {
        float4 o;
        o.x = acc[i * 4 + 0] * inv;
        o.y = acc[i * 4 + 1] * inv;
        o.z = acc[i * 4 + 2] * inv;
        o.w = acc[i * 4 + 3] * inv;
        *(float4*)(yp + i * 4) = o;
    }
}

// =============================================================
// Kernel 3: output projection.  out = Y @ Wo + bo, plain [M, C] layout.
// =============================================================
__global__ __launch_bounds__(256) void oproj_kernel(
    const float* __restrict__ W, const float* __restrict__ bias,
    float* __restrict__ out)
{
    __shared__ __align__(16) float As[BK][BM];
    __shared__ __align__(16) float Bs[BK][BN];

    const int tid = threadIdx.x;
    const int m0 = blockIdx.y * BM;
    const int n0 = blockIdx.x * BN;

    const int arow = tid >> 1;
    const int acol = (tid & 1) * 4;
    const int brow = tid >> 5;
    const int bcol = (tid & 31) * 4;

    const int ty = tid >> 4;
    const int tx = tid & 15;

    float acc[8][8];
    #pragma unroll
    for (int i = 0; i < 8; i++)
        #pragma unroll
        for (int j = 0; j < 8; j++) acc[i][j] = 0.f;

    for (int k0 = 0; k0 < EMB; k0 += BK) {
        float4 av = *(const float4*)(g_y + (size_t)(m0 + arow) * EMB + k0 + acol);
        float4 bv = *(const float4*)(W + (size_t)(k0 + brow) * EMB + n0 + bcol);
        As[acol + 0][arow] = av.x;
        As[acol + 1][arow] = av.y;
        As[acol + 2][arow] = av.z;
        As[acol + 3][arow] = av.w;
        *(float4*)&Bs[brow][bcol] = bv;
        __syncthreads();

        #pragma unroll
        for (int k = 0; k < BK; k++) {
            float a[8], b[8];
            *(float4*)(a)     = *(const float4*)&As[k][ty * 4];
            *(float4*)(a + 4) = *(const float4*)&As[k][64 + ty * 4];
            *(float4*)(b)     = *(const float4*)&Bs[k][tx * 4];
            *(float4*)(b + 4) = *(const float4*)&Bs[k][64 + tx * 4];
            #pragma unroll
            for (int i = 0; i < 8; i++)
                #pragma unroll
                for (int j = 0; j < 8; j++) acc[i][j] += a[i] * b[j];
        }
        __syncthreads();
    }

    #pragma unroll
    for (int i = 0; i < 8; i++) {
        const int rr = ((i < 4) ? (ty * 4 + i) : (64 + ty * 4 + i - 4));
        const int m = m0 + rr;
        #pragma unroll
        for (int j = 0; j < 8; j++) {
            const int cc = ((j < 4) ? (tx * 4 + j) : (64 + tx * 4 + j - 4));
            const int n = n0 + cc;
            out[(size_t)m * EMB + n] = acc[i][j] + bias[n];
        }
    }
}

// =============================================================
extern "C" void kernel_launch(void* const* d_in, const int* in_sizes, int n_in,
                              void* d_out, int out_size)
{
    const float* x  = (const float*)d_in[0];
    const float* Wq = (const float*)d_in[1];
    const float* bq = (const float*)d_in[2];
    const float* Wk = (const float*)d_in[3];
    const float* bk = (const float*)d_in[4];
    const float* Wv = (const float*)d_in[5];
    const float* bv = (const float*)d_in[6];
    const float* Wo = (const float*)d_in[7];
    const float* bo = (const float*)d_in[8];
    float* out = (float*)d_out;

    dim3 gemm_grid(EMB / BN, MTOT / BM, 3);      // (8, 64, 3)
    qkv_kernel<<<gemm_grid, 256>>>(x, Wq, Wk, Wv, bq, bk, bv);

    dim3 attn_grid(SEQ / FM, BATCH * NHEAD);     // (16, 64)
    attn_kernel<<<attn_grid, 128>>>();

    dim3 oproj_grid(EMB / BN, MTOT / BM);        // (8, 64)
    oproj_kernel<<<oproj_grid, 256>>>(Wo, bo, out);
}

// round 3
// speedup vs baseline: 1.6645x; 1.6645x over previous
#include <cuda_runtime.h>
#include <cuda_bf16.h>
#include <cstdint>
#include <math.h>

// ---------------- problem dims ----------------
#define BATCH 4
#define SEQ   2048
#define EMB   1024
#define NHEAD 16
#define HSZ   64
#define MTOT  (BATCH * SEQ)   // 8192

// ---------------- device scratch (no runtime allocation) ----------------
__device__ __align__(128) float g_q[(size_t)BATCH * NHEAD * SEQ * HSZ];
__device__ __align__(128) float g_k[(size_t)BATCH * NHEAD * SEQ * HSZ];
__device__ __align__(128) float g_v[(size_t)BATCH * NHEAD * SEQ * HSZ];
__device__ __align__(128) float g_y[(size_t)MTOT * EMB];

// ---------------- helpers ----------------
__device__ __forceinline__ uint32_t f2tf32(float f) {
    uint32_t r;
    asm("cvt.rna.tf32.f32 %0, %1;" : "=r"(r) : "f"(f));
    return r;
}

__device__ __forceinline__ void mma_tf32(float* d, const uint32_t* a, const uint32_t* b) {
    asm volatile(
        "mma.sync.aligned.m16n8k8.row.col.f32.tf32.tf32.f32 "
        "{%0,%1,%2,%3}, {%4,%5,%6,%7}, {%8,%9}, {%0,%1,%2,%3};"
        : "+f"(d[0]), "+f"(d[1]), "+f"(d[2]), "+f"(d[3])
        : "r"(a[0]), "r"(a[1]), "r"(a[2]), "r"(a[3]), "r"(b[0]), "r"(b[1]));
}

// ---------------- GEMM config ----------------
// CTA: 128x128 tile, 256 threads = 8 warps in 2(m) x 4(n); warp tile 64x32.
// K chunk = 32 (4 mma k-steps of 8).
#define APAD 36    // As row stride (floats): banks = 4m+k -> conflict-free frags
#define BPAD 136   // Bs row stride (floats): banks = 8k+n -> conflict-free frags

// =============================================================
// tf32 mma.sync GEMM.
// MODE 0: qkv (blockIdx.z selects matrix; scatter to [B,H,T,HS])
// MODE 1: output projection (A = g_y; writes d_out)
// W layout is the original [K][N] row-major (no transpose needed: B fragment
// reads are [k][n]-indexed).
// =============================================================
template <int MODE>
__global__ __launch_bounds__(256, 2) void gemm_kernel(
    const float* __restrict__ Ain, const float* __restrict__ W0,
    const float* __restrict__ W1, const float* __restrict__ W2,
    const float* __restrict__ bias0, const float* __restrict__ bias1,
    const float* __restrict__ bias2, float* __restrict__ outp)
{
    __shared__ uint32_t As[128 * APAD];
    __shared__ uint32_t Bs[32 * BPAD];
    __shared__ float bias_s[128];

    const int tid  = threadIdx.x;
    const int wid  = tid >> 5;
    const int lane = tid & 31;
    const int wm   = (wid >> 2) * 64;   // warp m offset (0, 64)
    const int wn   = (wid & 3) * 32;    // warp n offset (0, 32, 64, 96)
    const int n0   = blockIdx.x * 128;
    const int m0   = blockIdx.y * 128;
    const int mat  = (MODE == 0) ? (int)blockIdx.z : 3;

    const float* A = (MODE == 0) ? Ain : g_y;
    const float* W = (MODE == 0) ? ((mat == 0) ? W0 : (mat == 1) ? W1 : W2) : W0;
    const float* bias = (MODE == 0) ? ((mat == 0) ? bias0 : (mat == 1) ? bias1 : bias2)
                                    : bias0;

    if (tid < 128) bias_s[tid] = bias[n0 + tid];

    float acc[4][4][4];
    #pragma unroll
    for (int i = 0; i < 4; i++)
        #pragma unroll
        for (int j = 0; j < 4; j++)
            #pragma unroll
            for (int c = 0; c < 4; c++) acc[i][j][c] = 0.f;

    // loader mappings (per chunk: A = 128x32, B = 32x128, 4 float4 each)
    const int a_row = tid >> 1;                 // used as idx>>3 pattern below
    (void)a_row;

    for (int c = 0; c < EMB / 32; ++c) {
        const int k0 = c * 32;
        __syncthreads();

        #pragma unroll
        for (int it = 0; it < 4; ++it) {
            // A: idx over 128 rows x 8 float4-cols
            int idx = it * 256 + tid;
            int row = idx >> 3;
            int kq  = idx & 7;
            float4 va = *(const float4*)(A + (size_t)(m0 + row) * EMB + k0 + kq * 4);
            uint4 ta;
            ta.x = f2tf32(va.x); ta.y = f2tf32(va.y);
            ta.z = f2tf32(va.z); ta.w = f2tf32(va.w);
            *(uint4*)&As[row * APAD + kq * 4] = ta;

            // B: idx over 32 k-rows x 32 float4-cols
            int kr = idx >> 5;
            int nq = idx & 31;
            float4 vb = *(const float4*)(W + (size_t)(k0 + kr) * EMB + n0 + nq * 4);
            uint4 tb;
            tb.x = f2tf32(vb.x); tb.y = f2tf32(vb.y);
            tb.z = f2tf32(vb.z); tb.w = f2tf32(vb.w);
            *(uint4*)&Bs[kr * BPAD + nq * 4] = tb;
        }
        __syncthreads();

        #pragma unroll
        for (int ks = 0; ks < 4; ++ks) {
            const int kk = ks * 8 + (lane & 3);
            uint32_t af[4][4], bf[4][2];
            #pragma unroll
            for (int mt = 0; mt < 4; ++mt) {
                const int r = wm + mt * 16 + (lane >> 2);
                af[mt][0] = As[r * APAD + kk];
                af[mt][1] = As[(r + 8) * APAD + kk];
                af[mt][2] = As[r * APAD + kk + 4];
                af[mt][3] = As[(r + 8) * APAD + kk + 4];
            }
            #pragma unroll
            for (int nt = 0; nt < 4; ++nt) {
                const int n = wn + nt * 8 + (lane >> 2);
                bf[nt][0] = Bs[kk * BPAD + n];
                bf[nt][1] = Bs[(kk + 4) * BPAD + n];
            }
            #pragma unroll
            for (int mt = 0; mt < 4; ++mt)
                #pragma unroll
                for (int nt = 0; nt < 4; ++nt)
                    mma_tf32(acc[mt][nt], af[mt], bf[nt]);
        }
    }

    // ---------------- epilogue ----------------
    #pragma unroll
    for (int mt = 0; mt < 4; ++mt) {
        #pragma unroll
        for (int ci = 0; ci < 2; ++ci) {   // c-pair: rows +0 / +8
            const int m = m0 + wm + mt * 16 + (lane >> 2) + ci * 8;
            #pragma unroll
            for (int nt = 0; nt < 4; ++nt) {
                const int nl = wn + nt * 8 + (lane & 3) * 2;  // local n (even)
                const int n  = n0 + nl;
                float2 o;
                o.x = acc[mt][nt][ci * 2 + 0] + bias_s[nl];
                o.y = acc[mt][nt][ci * 2 + 1] + bias_s[nl + 1];
                if (MODE == 0) {
                    const int b = m >> 11;
                    const int t = m & (SEQ - 1);
                    const int h = n >> 6;
                    const int d = n & (HSZ - 1);
                    float* dst = (mat == 0) ? g_q : (mat == 1) ? g_k : g_v;
                    *(float2*)(dst + ((((size_t)b * NHEAD + h) * SEQ) + t) * HSZ + d) = o;
                } else {
                    *(float2*)(outp + (size_t)m * EMB + n) = o;
                }
            }
        }
    }
}

// =============================================================
// causal flash attention (fp32 SIMT) — unchanged.
// =============================================================
#define FM 128
#define FN 32

__global__ __launch_bounds__(128) void attn_kernel()
{
    const int bh  = blockIdx.y;
    const int tq  = blockIdx.x * FM + threadIdx.x;
    const size_t base = (size_t)bh * SEQ * HSZ;
    const float* Kp = g_k + base;
    const float* Vp = g_v + base;

    __shared__ __align__(16) float Ks[FN][HSZ];
    __shared__ __align__(16) float Vs[FN][HSZ];

    float q[HSZ];
    {
        const float* Qp = g_q + base + (size_t)tq * HSZ;
        #pragma unroll
        for (int i = 0; i < HSZ / 4; i++) {
            float4 v4 = *(const float4*)(Qp + i * 4);
            q[i * 4 + 0] = v4.x * 0.125f;
            q[i * 4 + 1] = v4.y * 0.125f;
            q[i * 4 + 2] = v4.z * 0.125f;
            q[i * 4 + 3] = v4.w * 0.125f;
        }
    }

    float acc[HSZ];
    #pragma unroll
    for (int d = 0; d < HSZ; d++) acc[d] = 0.f;
    float mx = -1e30f, l = 0.f;

    const int kend = blockIdx.x * FM + FM;
    for (int kb = 0; kb < kend; kb += FN) {
        __syncthreads();
        for (int i = threadIdx.x; i < FN * HSZ / 4; i += FM) {
            ((float4*)&Ks[0][0])[i] = *(const float4*)(Kp + (size_t)kb * HSZ + i * 4);
            ((float4*)&Vs[0][0])[i] = *(const float4*)(Vp + (size_t)kb * HSZ + i * 4);
        }
        __syncthreads();

        float s[FN];
        #pragma unroll 4
        for (int j = 0; j < FN; j++) {
            const float4* krow = (const float4*)Ks[j];
            float ss = 0.f;
            #pragma unroll
            for (int d4 = 0; d4 < HSZ / 4; d4++) {
                float4 kv = krow[d4];
                ss += q[d4 * 4 + 0] * kv.x;
                ss += q[d4 * 4 + 1] * kv.y;
                ss += q[d4 * 4 + 2] * kv.z;
                ss += q[d4 * 4 + 3] * kv.w;
            }
            s[j] = ((kb + j) <= tq) ? ss : -1e30f;
        }

        float mnew = mx;
        #pragma unroll
        for (int j = 0; j < FN; j++) mnew = fmaxf(mnew, s[j]);
        const float corr = __expf(mx - mnew);
        mx = mnew;

        float psum = 0.f;
        #pragma unroll
        for (int j = 0; j < FN; j++) {
            s[j] = __expf(s[j] - mnew);
            psum += s[j];
        }
        l = l * corr + psum;

        #pragma unroll
        for (int d = 0; d < HSZ; d++) acc[d] *= corr;

        #pragma unroll 4
        for (int j = 0; j < FN; j++) {
            const float p = s[j];
            const float4* vrow = (const float4*)Vs[j];
            #pragma unroll
            for (int d4 = 0; d4 < HSZ / 4; d4++) {
                float4 vv = vrow[d4];
                acc[d4 * 4 + 0] += p * vv.x;
                acc[d4 * 4 + 1] += p * vv.y;
                acc[d4 * 4 + 2] += p * vv.z;
                acc[d4 * 4 + 3] += p * vv.w;
            }
        }
    }

    const float inv = 1.f / l;
    const int bidx = bh / NHEAD;
    const int h    = bh % NHEAD;
    float* yp = g_y + ((size_t)bidx * SEQ + tq) * EMB + h * HSZ;
    #pragma unroll
    for (int i = 0; i < HSZ / 4; i++) {
        float4 o;
        o.x = acc[i * 4 + 0] * inv;
        o.y = acc[i * 4 + 1] * inv;
        o.z = acc[i * 4 + 2] * inv;
        o.w = acc[i * 4 + 3] * inv;
        *(float4*)(yp + i * 4) = o;
    }
}

// =============================================================
extern "C" void kernel_launch(void* const* d_in, const int* in_sizes, int n_in,
                              void* d_out, int out_size)
{
    const float* x  = (const float*)d_in[0];
    const float* Wq = (const float*)d_in[1];
    const float* bq = (const float*)d_in[2];
    const float* Wk = (const float*)d_in[3];
    const float* bk = (const float*)d_in[4];
    const float* Wv = (const float*)d_in[5];
    const float* bv = (const float*)d_in[6];
    const float* Wo = (const float*)d_in[7];
    const float* bo = (const float*)d_in[8];
    float* out = (float*)d_out;

    dim3 qkv_grid(EMB / 128, MTOT / 128, 3);    // (8, 64, 3)
    gemm_kernel<0><<<qkv_grid, 256>>>(x, Wq, Wk, Wv, bq, bk, bv, nullptr);

    dim3 attn_grid(SEQ / FM, BATCH * NHEAD);    // (16, 64)
    attn_kernel<<<attn_grid, 128>>>();

    dim3 oproj_grid(EMB / 128, MTOT / 128);     // (8, 64)
    gemm_kernel<1><<<oproj_grid, 256>>>(nullptr, Wo, nullptr, nullptr, bo, nullptr, nullptr, out);
}

// round 4
// speedup vs baseline: 3.8286x; 2.3001x over previous
#include <cuda_runtime.h>
#include <cuda_bf16.h>
#include <cstdint>
#include <math.h>

// ---------------- problem dims ----------------
#define BATCH 4
#define SEQ   2048
#define EMB   1024
#define NHEAD 16
#define HSZ   64
#define MTOT  (BATCH * SEQ)   // 8192

// ---------------- device scratch (no runtime allocation) ----------------
__device__ __align__(128) float g_q[(size_t)BATCH * NHEAD * SEQ * HSZ];
__device__ __align__(128) float g_k[(size_t)BATCH * NHEAD * SEQ * HSZ];
__device__ __align__(128) float g_v[(size_t)BATCH * NHEAD * SEQ * HSZ];
__device__ __align__(128) float g_y[(size_t)MTOT * EMB];

// ---------------- helpers ----------------
__device__ __forceinline__ uint32_t f2tf32(float f) {
    uint32_t r;
    asm("cvt.rna.tf32.f32 %0, %1;" : "=r"(r) : "f"(f));
    return r;
}

__device__ __forceinline__ void mma_tf32(float* d, const uint32_t* a, const uint32_t* b) {
    asm volatile(
        "mma.sync.aligned.m16n8k8.row.col.f32.tf32.tf32.f32 "
        "{%0,%1,%2,%3}, {%4,%5,%6,%7}, {%8,%9}, {%0,%1,%2,%3};"
        : "+f"(d[0]), "+f"(d[1]), "+f"(d[2]), "+f"(d[3])
        : "r"(a[0]), "r"(a[1]), "r"(a[2]), "r"(a[3]), "r"(b[0]), "r"(b[1]));
}

// =============================================================
// tf32 mma.sync GEMM (unchanged from round 3).
// =============================================================
#define APAD 36
#define BPAD 136

template <int MODE>
__global__ __launch_bounds__(256, 2) void gemm_kernel(
    const float* __restrict__ Ain, const float* __restrict__ W0,
    const float* __restrict__ W1, const float* __restrict__ W2,
    const float* __restrict__ bias0, const float* __restrict__ bias1,
    const float* __restrict__ bias2, float* __restrict__ outp)
{
    __shared__ uint32_t As[128 * APAD];
    __shared__ uint32_t Bs[32 * BPAD];
    __shared__ float bias_s[128];

    const int tid  = threadIdx.x;
    const int wid  = tid >> 5;
    const int lane = tid & 31;
    const int wm   = (wid >> 2) * 64;
    const int wn   = (wid & 3) * 32;
    const int n0   = blockIdx.x * 128;
    const int m0   = blockIdx.y * 128;
    const int mat  = (MODE == 0) ? (int)blockIdx.z : 3;

    const float* A = (MODE == 0) ? Ain : g_y;
    const float* W = (MODE == 0) ? ((mat == 0) ? W0 : (mat == 1) ? W1 : W2) : W0;
    const float* bias = (MODE == 0) ? ((mat == 0) ? bias0 : (mat == 1) ? bias1 : bias2)
                                    : bias0;

    if (tid < 128) bias_s[tid] = bias[n0 + tid];

    float acc[4][4][4];
    #pragma unroll
    for (int i = 0; i < 4; i++)
        #pragma unroll
        for (int j = 0; j < 4; j++)
            #pragma unroll
            for (int c = 0; c < 4; c++) acc[i][j][c] = 0.f;

    for (int c = 0; c < EMB / 32; ++c) {
        const int k0 = c * 32;
        __syncthreads();

        #pragma unroll
        for (int it = 0; it < 4; ++it) {
            int idx = it * 256 + tid;
            int row = idx >> 3;
            int kq  = idx & 7;
            float4 va = *(const float4*)(A + (size_t)(m0 + row) * EMB + k0 + kq * 4);
            uint4 ta;
            ta.x = f2tf32(va.x); ta.y = f2tf32(va.y);
            ta.z = f2tf32(va.z); ta.w = f2tf32(va.w);
            *(uint4*)&As[row * APAD + kq * 4] = ta;

            int kr = idx >> 5;
            int nq = idx & 31;
            float4 vb = *(const float4*)(W + (size_t)(k0 + kr) * EMB + n0 + nq * 4);
            uint4 tb;
            tb.x = f2tf32(vb.x); tb.y = f2tf32(vb.y);
            tb.z = f2tf32(vb.z); tb.w = f2tf32(vb.w);
            *(uint4*)&Bs[kr * BPAD + nq * 4] = tb;
        }
        __syncthreads();

        #pragma unroll
        for (int ks = 0; ks < 4; ++ks) {
            const int kk = ks * 8 + (lane & 3);
            uint32_t af[4][4], bf[4][2];
            #pragma unroll
            for (int mt = 0; mt < 4; ++mt) {
                const int r = wm + mt * 16 + (lane >> 2);
                af[mt][0] = As[r * APAD + kk];
                af[mt][1] = As[(r + 8) * APAD + kk];
                af[mt][2] = As[r * APAD + kk + 4];
                af[mt][3] = As[(r + 8) * APAD + kk + 4];
            }
            #pragma unroll
            for (int nt = 0; nt < 4; ++nt) {
                const int n = wn + nt * 8 + (lane >> 2);
                bf[nt][0] = Bs[kk * BPAD + n];
                bf[nt][1] = Bs[(kk + 4) * BPAD + n];
            }
            #pragma unroll
            for (int mt = 0; mt < 4; ++mt)
                #pragma unroll
                for (int nt = 0; nt < 4; ++nt)
                    mma_tf32(acc[mt][nt], af[mt], bf[nt]);
        }
    }

    #pragma unroll
    for (int mt = 0; mt < 4; ++mt) {
        #pragma unroll
        for (int ci = 0; ci < 2; ++ci) {
            const int m = m0 + wm + mt * 16 + (lane >> 2) + ci * 8;
            #pragma unroll
            for (int nt = 0; nt < 4; ++nt) {
                const int nl = wn + nt * 8 + (lane & 3) * 2;
                const int n  = n0 + nl;
                float2 o;
                o.x = acc[mt][nt][ci * 2 + 0] + bias_s[nl];
                o.y = acc[mt][nt][ci * 2 + 1] + bias_s[nl + 1];
                if (MODE == 0) {
                    const int b = m >> 11;
                    const int t = m & (SEQ - 1);
                    const int h = n >> 6;
                    const int d = n & (HSZ - 1);
                    float* dst = (mat == 0) ? g_q : (mat == 1) ? g_k : g_v;
                    *(float2*)(dst + ((((size_t)b * NHEAD + h) * SEQ) + t) * HSZ + d) = o;
                } else {
                    *(float2*)(outp + (size_t)m * EMB + n) = o;
                }
            }
        }
    }
}

// =============================================================
// tensor-core causal flash attention (tf32 mma.sync).
// CTA: 64 queries of one (b,h). 4 warps x 16 query rows.
// K/V tiles: 64 keys. Online softmax in accumulator layout.
// =============================================================
#define KSTRIDE 68   // Ks/Ps/Qs row stride (== 4 mod 32 -> conflict-free frags)
#define VSTRIDE 72   // Vs row stride      (== 8 mod 32 -> conflict-free frags)
#define ATT_SMEM_BYTES ((64 * KSTRIDE + 64 * VSTRIDE + 4 * 16 * KSTRIDE) * 4)  // 53248

__global__ __launch_bounds__(128) void attn_mma_kernel()
{
    extern __shared__ uint32_t sm[];
    uint32_t* Ks = sm;                       // [64][KSTRIDE] (also Q staging)
    uint32_t* Vs = sm + 64 * KSTRIDE;        // [64][VSTRIDE]
    const int tid  = threadIdx.x;
    const int wid  = tid >> 5;
    const int lane = tid & 31;
    const int g    = lane >> 2;
    const int qd   = lane & 3;
    uint32_t* Ps = sm + 64 * KSTRIDE + 64 * VSTRIDE + wid * 16 * KSTRIDE; // [16][KSTRIDE]

    const int bh = blockIdx.y;
    const int q0 = blockIdx.x * 64;
    const int wq = wid * 16;
    const size_t base = (size_t)bh * SEQ * HSZ;
    const float* Qp = g_q + base;
    const float* Kp = g_k + base;
    const float* Vp = g_v + base;

    // ---- stage Q tile (scaled by 1/8) into Ks, read fragments ----
    #pragma unroll
    for (int it = 0; it < 8; ++it) {
        int idx = it * 128 + tid;
        int row = idx >> 4;
        int c4  = idx & 15;
        float4 v = *(const float4*)(Qp + (size_t)(q0 + row) * HSZ + c4 * 4);
        uint4 t;
        t.x = f2tf32(v.x * 0.125f); t.y = f2tf32(v.y * 0.125f);
        t.z = f2tf32(v.z * 0.125f); t.w = f2tf32(v.w * 0.125f);
        *(uint4*)&Ks[row * KSTRIDE + c4 * 4] = t;
    }
    __syncthreads();

    uint32_t qf[8][4];
    #pragma unroll
    for (int ks = 0; ks < 8; ++ks) {
        qf[ks][0] = Ks[(wq + g) * KSTRIDE + ks * 8 + qd];
        qf[ks][1] = Ks[(wq + g + 8) * KSTRIDE + ks * 8 + qd];
        qf[ks][2] = Ks[(wq + g) * KSTRIDE + ks * 8 + qd + 4];
        qf[ks][3] = Ks[(wq + g + 8) * KSTRIDE + ks * 8 + qd + 4];
    }
    __syncthreads();

    float of[8][4];
    #pragma unroll
    for (int nt = 0; nt < 8; ++nt)
        #pragma unroll
        for (int c = 0; c < 4; ++c) of[nt][c] = 0.f;
    float m0 = -1e30f, m1 = -1e30f, l0 = 0.f, l1 = 0.f;

    const int ntile = (q0 >> 6) + 1;
    for (int kt = 0; kt < ntile; ++kt) {
        const int kb = kt * 64;

        // ---- load K/V tile (tf32-converted) ----
        #pragma unroll
        for (int it = 0; it < 8; ++it) {
            int idx = it * 128 + tid;
            int row = idx >> 4;
            int c4  = idx & 15;
            float4 kv = *(const float4*)(Kp + (size_t)(kb + row) * HSZ + c4 * 4);
            uint4 tk;
            tk.x = f2tf32(kv.x); tk.y = f2tf32(kv.y);
            tk.z = f2tf32(kv.z); tk.w = f2tf32(kv.w);
            *(uint4*)&Ks[row * KSTRIDE + c4 * 4] = tk;
            float4 vv = *(const float4*)(Vp + (size_t)(kb + row) * HSZ + c4 * 4);
            uint4 tv;
            tv.x = f2tf32(vv.x); tv.y = f2tf32(vv.y);
            tv.z = f2tf32(vv.z); tv.w = f2tf32(vv.w);
            *(uint4*)&Vs[row * VSTRIDE + c4 * 4] = tv;
        }
        __syncthreads();

        // ---- S = Q K^T ----
        float sf[8][4];
        #pragma unroll
        for (int nt = 0; nt < 8; ++nt) {
            float s4[4] = {0.f, 0.f, 0.f, 0.f};
            #pragma unroll
            for (int ks = 0; ks < 8; ++ks) {
                uint32_t bf[2];
                bf[0] = Ks[(nt * 8 + g) * KSTRIDE + ks * 8 + qd];
                bf[1] = Ks[(nt * 8 + g) * KSTRIDE + ks * 8 + qd + 4];
                mma_tf32(s4, qf[ks], bf);
            }
            if (kt == ntile - 1) {
                const int kl = nt * 8 + 2 * qd;
                if (kl     > wq + g)     s4[0] = -1e30f;
                if (kl + 1 > wq + g)     s4[1] = -1e30f;
                if (kl     > wq + g + 8) s4[2] = -1e30f;
                if (kl + 1 > wq + g + 8) s4[3] = -1e30f;
            }
            sf[nt][0] = s4[0]; sf[nt][1] = s4[1];
            sf[nt][2] = s4[2]; sf[nt][3] = s4[3];
        }

        // ---- online softmax ----
        float t0 = -1e30f, t1 = -1e30f;
        #pragma unroll
        for (int nt = 0; nt < 8; ++nt) {
            t0 = fmaxf(t0, fmaxf(sf[nt][0], sf[nt][1]));
            t1 = fmaxf(t1, fmaxf(sf[nt][2], sf[nt][3]));
        }
        t0 = fmaxf(t0, __shfl_xor_sync(0xffffffffu, t0, 1));
        t0 = fmaxf(t0, __shfl_xor_sync(0xffffffffu, t0, 2));
        t1 = fmaxf(t1, __shfl_xor_sync(0xffffffffu, t1, 1));
        t1 = fmaxf(t1, __shfl_xor_sync(0xffffffffu, t1, 2));

        const float mn0 = fmaxf(m0, t0);
        const float mn1 = fmaxf(m1, t1);
        const float cr0 = __expf(m0 - mn0);
        const float cr1 = __expf(m1 - mn1);
        m0 = mn0; m1 = mn1;

        float ps0 = 0.f, ps1 = 0.f;
        #pragma unroll
        for (int nt = 0; nt < 8; ++nt) {
            sf[nt][0] = __expf(sf[nt][0] - mn0);
            sf[nt][1] = __expf(sf[nt][1] - mn0);
            sf[nt][2] = __expf(sf[nt][2] - mn1);
            sf[nt][3] = __expf(sf[nt][3] - mn1);
            ps0 += sf[nt][0] + sf[nt][1];
            ps1 += sf[nt][2] + sf[nt][3];
        }
        ps0 += __shfl_xor_sync(0xffffffffu, ps0, 1);
        ps0 += __shfl_xor_sync(0xffffffffu, ps0, 2);
        ps1 += __shfl_xor_sync(0xffffffffu, ps1, 1);
        ps1 += __shfl_xor_sync(0xffffffffu, ps1, 2);
        l0 = l0 * cr0 + ps0;
        l1 = l1 * cr1 + ps1;

        #pragma unroll
        for (int nt = 0; nt < 8; ++nt) {
            of[nt][0] *= cr0; of[nt][1] *= cr0;
            of[nt][2] *= cr1; of[nt][3] *= cr1;
        }

        // ---- store P (tf32) to per-warp smem tile ----
        #pragma unroll
        for (int nt = 0; nt < 8; ++nt) {
            uint2 p0, p1;
            p0.x = f2tf32(sf[nt][0]); p0.y = f2tf32(sf[nt][1]);
            p1.x = f2tf32(sf[nt][2]); p1.y = f2tf32(sf[nt][3]);
            *(uint2*)&Ps[g * KSTRIDE + nt * 8 + 2 * qd] = p0;
            *(uint2*)&Ps[(g + 8) * KSTRIDE + nt * 8 + 2 * qd] = p1;
        }
        __syncwarp();

        // ---- O += P V ----
        #pragma unroll
        for (int ks = 0; ks < 8; ++ks) {
            uint32_t af[4];
            af[0] = Ps[g * KSTRIDE + ks * 8 + qd];
            af[1] = Ps[(g + 8) * KSTRIDE + ks * 8 + qd];
            af[2] = Ps[g * KSTRIDE + ks * 8 + qd + 4];
            af[3] = Ps[(g + 8) * KSTRIDE + ks * 8 + qd + 4];
            #pragma unroll
            for (int nt = 0; nt < 8; ++nt) {
                uint32_t bf[2];
                bf[0] = Vs[(ks * 8 + qd) * VSTRIDE + nt * 8 + g];
                bf[1] = Vs[(ks * 8 + qd + 4) * VSTRIDE + nt * 8 + g];
                mma_tf32(of[nt], af, bf);
            }
        }
        __syncthreads();
    }

    // ---- epilogue: normalize, write y [B,T,C] ----
    const float inv0 = 1.f / l0;
    const float inv1 = 1.f / l1;
    const int b = bh / NHEAD;
    const int h = bh % NHEAD;
    const int r0 = q0 + wq + g;
    float* y0 = g_y + ((size_t)b * SEQ + r0) * EMB + h * HSZ;
    float* y1 = g_y + ((size_t)b * SEQ + r0 + 8) * EMB + h * HSZ;
    #pragma unroll
    for (int nt = 0; nt < 8; ++nt) {
        float2 o0, o1;
        o0.x = of[nt][0] * inv0; o0.y = of[nt][1] * inv0;
        o1.x = of[nt][2] * inv1; o1.y = of[nt][3] * inv1;
        *(float2*)(y0 + nt * 8 + 2 * qd) = o0;
        *(float2*)(y1 + nt * 8 + 2 * qd) = o1;
    }
}

// =============================================================
extern "C" void kernel_launch(void* const* d_in, const int* in_sizes, int n_in,
                              void* d_out, int out_size)
{
    const float* x  = (const float*)d_in[0];
    const float* Wq = (const float*)d_in[1];
    const float* bq = (const float*)d_in[2];
    const float* Wk = (const float*)d_in[3];
    const float* bk = (const float*)d_in[4];
    const float* Wv = (const float*)d_in[5];
    const float* bv = (const float*)d_in[6];
    const float* Wo = (const float*)d_in[7];
    const float* bo = (const float*)d_in[8];
    float* out = (float*)d_out;

    cudaFuncSetAttribute(attn_mma_kernel, cudaFuncAttributeMaxDynamicSharedMemorySize,
                         ATT_SMEM_BYTES);

    dim3 qkv_grid(EMB / 128, MTOT / 128, 3);
    gemm_kernel<0><<<qkv_grid, 256>>>(x, Wq, Wk, Wv, bq, bk, bv, nullptr);

    dim3 attn_grid(SEQ / 64, BATCH * NHEAD);   // (32, 64)
    attn_mma_kernel<<<attn_grid, 128, ATT_SMEM_BYTES>>>();

    dim3 oproj_grid(EMB / 128, MTOT / 128);
    gemm_kernel<1><<<oproj_grid, 256>>>(nullptr, Wo, nullptr, nullptr, bo, nullptr, nullptr, out);
}

// round 5
// speedup vs baseline: 4.0970x; 1.0701x over previous
#include <cuda_runtime.h>
#include <cuda_bf16.h>
#include <cstdint>
#include <math.h>

// ---------------- problem dims ----------------
#define BATCH 4
#define SEQ   2048
#define EMB   1024
#define NHEAD 16
#define HSZ   64
#define MTOT  (BATCH * SEQ)   // 8192

// ---------------- device scratch (no runtime allocation) ----------------
__device__ __align__(128) float g_q[(size_t)BATCH * NHEAD * SEQ * HSZ];
__device__ __align__(128) float g_k[(size_t)BATCH * NHEAD * SEQ * HSZ];
__device__ __align__(128) float g_v[(size_t)BATCH * NHEAD * SEQ * HSZ];
__device__ __align__(128) float g_y[(size_t)MTOT * EMB];

// ---------------- helpers ----------------
__device__ __forceinline__ uint32_t f2tf32(float f) {
    uint32_t r;
    asm("cvt.rna.tf32.f32 %0, %1;" : "=r"(r) : "f"(f));
    return r;
}

__device__ __forceinline__ void mma_tf32(float* d, const uint32_t* a, const uint32_t* b) {
    asm volatile(
        "mma.sync.aligned.m16n8k8.row.col.f32.tf32.tf32.f32 "
        "{%0,%1,%2,%3}, {%4,%5,%6,%7}, {%8,%9}, {%0,%1,%2,%3};"
        : "+f"(d[0]), "+f"(d[1]), "+f"(d[2]), "+f"(d[3])
        : "r"(a[0]), "r"(a[1]), "r"(a[2]), "r"(a[3]), "r"(b[0]), "r"(b[1]));
}

// ---------------- GEMM config ----------------
// CTA: 128x128 tile, 128 threads = 4 warps in 2(m) x 2(n); warp tile 64x64.
// K chunk = 32. Double-buffered smem, register prefetch of next chunk.
#define APAD 36     // As row stride (words)
#define BPAD 136    // Bs row stride (words)
#define ABUF (128 * APAD)   // 4608 words per buffer
#define BBUF (32 * BPAD)    // 4352 words per buffer
#define GEMM_SMEM_BYTES ((2 * ABUF + 2 * BBUF + 128) * 4)   // 72192

// =============================================================
// tf32 mma.sync GEMM, software pipelined.
// MODE 0: qkv (blockIdx.z selects matrix; scatter to [B,H,T,HS])
// MODE 1: output projection (A = g_y; writes d_out)
// =============================================================
template <int MODE>
__global__ __launch_bounds__(128) void gemm_kernel(
    const float* __restrict__ Ain, const float* __restrict__ W0,
    const float* __restrict__ W1, const float* __restrict__ W2,
    const float* __restrict__ bias0, const float* __restrict__ bias1,
    const float* __restrict__ bias2, float* __restrict__ outp)
{
    extern __shared__ uint32_t dynsm[];
    uint32_t* As = dynsm;                       // [2][128*APAD]
    uint32_t* Bs = dynsm + 2 * ABUF;            // [2][32*BPAD]
    float* bias_s = (float*)(dynsm + 2 * ABUF + 2 * BBUF);

    const int tid  = threadIdx.x;
    const int wid  = tid >> 5;
    const int lane = tid & 31;
    const int g    = lane >> 2;
    const int qd   = lane & 3;
    const int wm   = (wid >> 1) * 64;
    const int wn   = (wid & 1) * 64;
    const int n0   = blockIdx.x * 128;
    const int m0   = blockIdx.y * 128;
    const int mat  = (MODE == 0) ? (int)blockIdx.z : 3;

    const float* A = (MODE == 0) ? Ain : g_y;
    const float* W = (MODE == 0) ? ((mat == 0) ? W0 : (mat == 1) ? W1 : W2) : W0;
    const float* bias = (MODE == 0) ? ((mat == 0) ? bias0 : (mat == 1) ? bias1 : bias2)
                                    : bias0;

    bias_s[tid] = bias[n0 + tid];

    float acc[4][8][4];
    #pragma unroll
    for (int i = 0; i < 4; i++)
        #pragma unroll
        for (int j = 0; j < 8; j++)
            #pragma unroll
            for (int c = 0; c < 4; c++) acc[i][j][c] = 0.f;

    // per-thread loader coordinates (8 float4 for A, 8 for B per chunk)
    float4 apf[8], bpf[8];

    #define LOAD_CHUNK(K0) do { \
        _Pragma("unroll") \
        for (int it = 0; it < 8; ++it) { \
            const int idx = it * 128 + tid; \
            apf[it] = *(const float4*)(A + (size_t)(m0 + (idx >> 3)) * EMB + (K0) + (idx & 7) * 4); \
            bpf[it] = *(const float4*)(W + (size_t)((K0) + (idx >> 5)) * EMB + n0 + (idx & 31) * 4); \
        } \
    } while (0)

    #define STORE_CHUNK(BUF) do { \
        uint32_t* Ab = As + (BUF) * ABUF; \
        uint32_t* Bb = Bs + (BUF) * BBUF; \
        _Pragma("unroll") \
        for (int it = 0; it < 8; ++it) { \
            const int idx = it * 128 + tid; \
            uint4 ta; \
            ta.x = f2tf32(apf[it].x); ta.y = f2tf32(apf[it].y); \
            ta.z = f2tf32(apf[it].z); ta.w = f2tf32(apf[it].w); \
            *(uint4*)&Ab[(idx >> 3) * APAD + (idx & 7) * 4] = ta; \
            uint4 tb; \
            tb.x = f2tf32(bpf[it].x); tb.y = f2tf32(bpf[it].y); \
            tb.z = f2tf32(bpf[it].z); tb.w = f2tf32(bpf[it].w); \
            *(uint4*)&Bb[(idx >> 5) * BPAD + (idx & 31) * 4] = tb; \
        } \
    } while (0)

    LOAD_CHUNK(0);
    STORE_CHUNK(0);
    __syncthreads();

    for (int c = 0; c < EMB / 32; ++c) {
        if (c < EMB / 32 - 1)
            LOAD_CHUNK((c + 1) * 32);

        const uint32_t* Ab = As + (c & 1) * ABUF;
        const uint32_t* Bb = Bs + (c & 1) * BBUF;

        #pragma unroll
        for (int ks = 0; ks < 4; ++ks) {
            const int kk = ks * 8 + qd;
            uint32_t af[4][4], bf[8][2];
            #pragma unroll
            for (int mt = 0; mt < 4; ++mt) {
                const int r = wm + mt * 16 + g;
                af[mt][0] = Ab[r * APAD + kk];
                af[mt][1] = Ab[(r + 8) * APAD + kk];
                af[mt][2] = Ab[r * APAD + kk + 4];
                af[mt][3] = Ab[(r + 8) * APAD + kk + 4];
            }
            #pragma unroll
            for (int nt = 0; nt < 8; ++nt) {
                const int n = wn + nt * 8 + g;
                bf[nt][0] = Bb[kk * BPAD + n];
                bf[nt][1] = Bb[(kk + 4) * BPAD + n];
            }
            #pragma unroll
            for (int mt = 0; mt < 4; ++mt)
                #pragma unroll
                for (int nt = 0; nt < 8; ++nt)
                    mma_tf32(acc[mt][nt], af[mt], bf[nt]);
        }

        if (c < EMB / 32 - 1)
            STORE_CHUNK((c + 1) & 1);
        __syncthreads();
    }

    #undef LOAD_CHUNK
    #undef STORE_CHUNK

    // ---------------- epilogue ----------------
    #pragma unroll
    for (int mt = 0; mt < 4; ++mt) {
        #pragma unroll
        for (int ci = 0; ci < 2; ++ci) {
            const int m = m0 + wm + mt * 16 + g + ci * 8;
            #pragma unroll
            for (int nt = 0; nt < 8; ++nt) {
                const int nl = wn + nt * 8 + qd * 2;
                const int n  = n0 + nl;
                float2 o;
                o.x = acc[mt][nt][ci * 2 + 0] + bias_s[nl];
                o.y = acc[mt][nt][ci * 2 + 1] + bias_s[nl + 1];
                if (MODE == 0) {
                    const int b = m >> 11;
                    const int t = m & (SEQ - 1);
                    const int h = n >> 6;
                    const int d = n & (HSZ - 1);
                    float* dst = (mat == 0) ? g_q : (mat == 1) ? g_k : g_v;
                    *(float2*)(dst + ((((size_t)b * NHEAD + h) * SEQ) + t) * HSZ + d) = o;
                } else {
                    *(float2*)(outp + (size_t)m * EMB + n) = o;
                }
            }
        }
    }
}

// =============================================================
// tensor-core causal flash attention (tf32 mma.sync) — unchanged.
// =============================================================
#define KSTRIDE 68
#define VSTRIDE 72
#define ATT_SMEM_BYTES ((64 * KSTRIDE + 64 * VSTRIDE + 4 * 16 * KSTRIDE) * 4)

__global__ __launch_bounds__(128) void attn_mma_kernel()
{
    extern __shared__ uint32_t sm[];
    uint32_t* Ks = sm;
    uint32_t* Vs = sm + 64 * KSTRIDE;
    const int tid  = threadIdx.x;
    const int wid  = tid >> 5;
    const int lane = tid & 31;
    const int g    = lane >> 2;
    const int qd   = lane & 3;
    uint32_t* Ps = sm + 64 * KSTRIDE + 64 * VSTRIDE + wid * 16 * KSTRIDE;

    const int bh = blockIdx.y;
    const int q0 = blockIdx.x * 64;
    const int wq = wid * 16;
    const size_t base = (size_t)bh * SEQ * HSZ;
    const float* Qp = g_q + base;
    const float* Kp = g_k + base;
    const float* Vp = g_v + base;

    #pragma unroll
    for (int it = 0; it < 8; ++it) {
        int idx = it * 128 + tid;
        int row = idx >> 4;
        int c4  = idx & 15;
        float4 v = *(const float4*)(Qp + (size_t)(q0 + row) * HSZ + c4 * 4);
        uint4 t;
        t.x = f2tf32(v.x * 0.125f); t.y = f2tf32(v.y * 0.125f);
        t.z = f2tf32(v.z * 0.125f); t.w = f2tf32(v.w * 0.125f);
        *(uint4*)&Ks[row * KSTRIDE + c4 * 4] = t;
    }
    __syncthreads();

    uint32_t qf[8][4];
    #pragma unroll
    for (int ks = 0; ks < 8; ++ks) {
        qf[ks][0] = Ks[(wq + g) * KSTRIDE + ks * 8 + qd];
        qf[ks][1] = Ks[(wq + g + 8) * KSTRIDE + ks * 8 + qd];
        qf[ks][2] = Ks[(wq + g) * KSTRIDE + ks * 8 + qd + 4];
        qf[ks][3] = Ks[(wq + g + 8) * KSTRIDE + ks * 8 + qd + 4];
    }
    __syncthreads();

    float of[8][4];
    #pragma unroll
    for (int nt = 0; nt < 8; ++nt)
        #pragma unroll
        for (int c = 0; c < 4; ++c) of[nt][c] = 0.f;
    float m0 = -1e30f, m1 = -1e30f, l0 = 0.f, l1 = 0.f;

    const int ntile = (q0 >> 6) + 1;
    for (int kt = 0; kt < ntile; ++kt) {
        const int kb = kt * 64;

        #pragma unroll
        for (int it = 0; it < 8; ++it) {
            int idx = it * 128 + tid;
            int row = idx >> 4;
            int c4  = idx & 15;
            float4 kv = *(const float4*)(Kp + (size_t)(kb + row) * HSZ + c4 * 4);
            uint4 tk;
            tk.x = f2tf32(kv.x); tk.y = f2tf32(kv.y);
            tk.z = f2tf32(kv.z); tk.w = f2tf32(kv.w);
            *(uint4*)&Ks[row * KSTRIDE + c4 * 4] = tk;
            float4 vv = *(const float4*)(Vp + (size_t)(kb + row) * HSZ + c4 * 4);
            uint4 tv;
            tv.x = f2tf32(vv.x); tv.y = f2tf32(vv.y);
            tv.z = f2tf32(vv.z); tv.w = f2tf32(vv.w);
            *(uint4*)&Vs[row * VSTRIDE + c4 * 4] = tv;
        }
        __syncthreads();

        float sf[8][4];
        #pragma unroll
        for (int nt = 0; nt < 8; ++nt) {
            float s4[4] = {0.f, 0.f, 0.f, 0.f};
            #pragma unroll
            for (int ks = 0; ks < 8; ++ks) {
                uint32_t bf[2];
                bf[0] = Ks[(nt * 8 + g) * KSTRIDE + ks * 8 + qd];
                bf[1] = Ks[(nt * 8 + g) * KSTRIDE + ks * 8 + qd + 4];
                mma_tf32(s4, qf[ks], bf);
            }
            if (kt == ntile - 1) {
                const int kl = nt * 8 + 2 * qd;
                if (kl     > wq + g)     s4[0] = -1e30f;
                if (kl + 1 > wq + g)     s4[1] = -1e30f;
                if (kl     > wq + g + 8) s4[2] = -1e30f;
                if (kl + 1 > wq + g + 8) s4[3] = -1e30f;
            }
            sf[nt][0] = s4[0]; sf[nt][1] = s4[1];
            sf[nt][2] = s4[2]; sf[nt][3] = s4[3];
        }

        float t0 = -1e30f, t1 = -1e30f;
        #pragma unroll
        for (int nt = 0; nt < 8; ++nt) {
            t0 = fmaxf(t0, fmaxf(sf[nt][0], sf[nt][1]));
            t1 = fmaxf(t1, fmaxf(sf[nt][2], sf[nt][3]));
        }
        t0 = fmaxf(t0, __shfl_xor_sync(0xffffffffu, t0, 1));
        t0 = fmaxf(t0, __shfl_xor_sync(0xffffffffu, t0, 2));
        t1 = fmaxf(t1, __shfl_xor_sync(0xffffffffu, t1, 1));
        t1 = fmaxf(t1, __shfl_xor_sync(0xffffffffu, t1, 2));

        const float mn0 = fmaxf(m0, t0);
        const float mn1 = fmaxf(m1, t1);
        const float cr0 = __expf(m0 - mn0);
        const float cr1 = __expf(m1 - mn1);
        m0 = mn0; m1 = mn1;

        float ps0 = 0.f, ps1 = 0.f;
        #pragma unroll
        for (int nt = 0; nt < 8; ++nt) {
            sf[nt][0] = __expf(sf[nt][0] - mn0);
            sf[nt][1] = __expf(sf[nt][1] - mn0);
            sf[nt][2] = __expf(sf[nt][2] - mn1);
            sf[nt][3] = __expf(sf[nt][3] - mn1);
            ps0 += sf[nt][0] + sf[nt][1];
            ps1 += sf[nt][2] + sf[nt][3];
        }
        ps0 += __shfl_xor_sync(0xffffffffu, ps0, 1);
        ps0 += __shfl_xor_sync(0xffffffffu, ps0, 2);
        ps1 += __shfl_xor_sync(0xffffffffu, ps1, 1);
        ps1 += __shfl_xor_sync(0xffffffffu, ps1, 2);
        l0 = l0 * cr0 + ps0;
        l1 = l1 * cr1 + ps1;

        #pragma unroll
        for (int nt = 0; nt < 8; ++nt) {
            of[nt][0] *= cr0; of[nt][1] *= cr0;
            of[nt][2] *= cr1; of[nt][3] *= cr1;
        }

        #pragma unroll
        for (int nt = 0; nt < 8; ++nt) {
            uint2 p0, p1;
            p0.x = f2tf32(sf[nt][0]); p0.y = f2tf32(sf[nt][1]);
            p1.x = f2tf32(sf[nt][2]); p1.y = f2tf32(sf[nt][3]);
            *(uint2*)&Ps[g * KSTRIDE + nt * 8 + 2 * qd] = p0;
            *(uint2*)&Ps[(g + 8) * KSTRIDE + nt * 8 + 2 * qd] = p1;
        }
        __syncwarp();

        #pragma unroll
        for (int ks = 0; ks < 8; ++ks) {
            uint32_t af[4];
            af[0] = Ps[g * KSTRIDE + ks * 8 + qd];
            af[1] = Ps[(g + 8) * KSTRIDE + ks * 8 + qd];
            af[2] = Ps[g * KSTRIDE + ks * 8 + qd + 4];
            af[3] = Ps[(g + 8) * KSTRIDE + ks * 8 + qd + 4];
            #pragma unroll
            for (int nt = 0; nt < 8; ++nt) {
                uint32_t bf[2];
                bf[0] = Vs[(ks * 8 + qd) * VSTRIDE + nt * 8 + g];
                bf[1] = Vs[(ks * 8 + qd + 4) * VSTRIDE + nt * 8 + g];
                mma_tf32(of[nt], af, bf);
            }
        }
        __syncthreads();
    }

    const float inv0 = 1.f / l0;
    const float inv1 = 1.f / l1;
    const int b = bh / NHEAD;
    const int h = bh % NHEAD;
    const int r0 = q0 + wq + g;
    float* y0 = g_y + ((size_t)b * SEQ + r0) * EMB + h * HSZ;
    float* y1 = g_y + ((size_t)b * SEQ + r0 + 8) * EMB + h * HSZ;
    #pragma unroll
    for (int nt = 0; nt < 8; ++nt) {
        float2 o0, o1;
        o0.x = of[nt][0] * inv0; o0.y = of[nt][1] * inv0;
        o1.x = of[nt][2] * inv1; o1.y = of[nt][3] * inv1;
        *(float2*)(y0 + nt * 8 + 2 * qd) = o0;
        *(float2*)(y1 + nt * 8 + 2 * qd) = o1;
    }
}

// =============================================================
extern "C" void kernel_launch(void* const* d_in, const int* in_sizes, int n_in,
                              void* d_out, int out_size)
{
    const float* x  = (const float*)d_in[0];
    const float* Wq = (const float*)d_in[1];
    const float* bq = (const float*)d_in[2];
    const float* Wk = (const float*)d_in[3];
    const float* bk = (const float*)d_in[4];
    const float* Wv = (const float*)d_in[5];
    const float* bv = (const float*)d_in[6];
    const float* Wo = (const float*)d_in[7];
    const float* bo = (const float*)d_in[8];
    float* out = (float*)d_out;

    cudaFuncSetAttribute(gemm_kernel<0>, cudaFuncAttributeMaxDynamicSharedMemorySize,
                         GEMM_SMEM_BYTES);
    cudaFuncSetAttribute(gemm_kernel<1>, cudaFuncAttributeMaxDynamicSharedMemorySize,
                         GEMM_SMEM_BYTES);
    cudaFuncSetAttribute(attn_mma_kernel, cudaFuncAttributeMaxDynamicSharedMemorySize,
                         ATT_SMEM_BYTES);

    dim3 qkv_grid(EMB / 128, MTOT / 128, 3);
    gemm_kernel<0><<<qkv_grid, 128, GEMM_SMEM_BYTES>>>(x, Wq, Wk, Wv, bq, bk, bv, nullptr);

    dim3 attn_grid(SEQ / 64, BATCH * NHEAD);
    attn_mma_kernel<<<attn_grid, 128, ATT_SMEM_BYTES>>>();

    dim3 oproj_grid(EMB / 128, MTOT / 128);
    gemm_kernel<1><<<oproj_grid, 128, GEMM_SMEM_BYTES>>>(nullptr, Wo, nullptr, nullptr, bo, nullptr, nullptr, out);
}

// round 6
// speedup vs baseline: 4.1075x; 1.0026x over previous
#include <cuda_runtime.h>
#include <cuda_bf16.h>
#include <cstdint>
#include <math.h>

// ---------------- problem dims ----------------
#define BATCH 4
#define SEQ   2048
#define EMB   1024
#define NHEAD 16
#define HSZ   64
#define MTOT  (BATCH * SEQ)   // 8192

// ---------------- device scratch (no runtime allocation) ----------------
__device__ __align__(128) float g_q[(size_t)BATCH * NHEAD * SEQ * HSZ];
__device__ __align__(128) float g_k[(size_t)BATCH * NHEAD * SEQ * HSZ];
__device__ __align__(128) float g_v[(size_t)BATCH * NHEAD * SEQ * HSZ];
__device__ __align__(128) float g_y[(size_t)MTOT * EMB];

// ---------------- helpers ----------------
__device__ __forceinline__ uint32_t f2tf32(float f) {
    uint32_t r;
    asm("cvt.rna.tf32.f32 %0, %1;" : "=r"(r) : "f"(f));
    return r;
}

__device__ __forceinline__ void mma_tf32(float* d, const uint32_t* a, const uint32_t* b) {
    asm volatile(
        "mma.sync.aligned.m16n8k8.row.col.f32.tf32.tf32.f32 "
        "{%0,%1,%2,%3}, {%4,%5,%6,%7}, {%8,%9}, {%0,%1,%2,%3};"
        : "+f"(d[0]), "+f"(d[1]), "+f"(d[2]), "+f"(d[3])
        : "r"(a[0]), "r"(a[1]), "r"(a[2]), "r"(a[3]), "r"(b[0]), "r"(b[1]));
}

// ---------------- GEMM config ----------------
// CTA: 128x128 tile, 128 threads = 4 warps in 2(m) x 2(n); warp tile 64x64.
// K chunk = 32. Double-buffered smem, register prefetch of next chunk.
#define APAD 36     // As row stride (words)
#define BPAD 136    // Bs row stride (words)
#define ABUF (128 * APAD)   // 4608 words per buffer
#define BBUF (32 * BPAD)    // 4352 words per buffer
#define GEMM_SMEM_BYTES ((2 * ABUF + 2 * BBUF + 128) * 4)   // 72192

// =============================================================
// tf32 mma.sync GEMM, software pipelined.
// MODE 0: qkv (blockIdx.z selects matrix; scatter to [B,H,T,HS])
// MODE 1: output projection (A = g_y; writes d_out)
// =============================================================
template <int MODE>
__global__ __launch_bounds__(128) void gemm_kernel(
    const float* __restrict__ Ain, const float* __restrict__ W0,
    const float* __restrict__ W1, const float* __restrict__ W2,
    const float* __restrict__ bias0, const float* __restrict__ bias1,
    const float* __restrict__ bias2, float* __restrict__ outp)
{
    extern __shared__ uint32_t dynsm[];
    uint32_t* As = dynsm;                       // [2][128*APAD]
    uint32_t* Bs = dynsm + 2 * ABUF;            // [2][32*BPAD]
    float* bias_s = (float*)(dynsm + 2 * ABUF + 2 * BBUF);

    const int tid  = threadIdx.x;
    const int wid  = tid >> 5;
    const int lane = tid & 31;
    const int g    = lane >> 2;
    const int qd   = lane & 3;
    const int wm   = (wid >> 1) * 64;
    const int wn   = (wid & 1) * 64;
    const int n0   = blockIdx.x * 128;
    const int m0   = blockIdx.y * 128;
    const int mat  = (MODE == 0) ? (int)blockIdx.z : 3;

    const float* A = (MODE == 0) ? Ain : g_y;
    const float* W = (MODE == 0) ? ((mat == 0) ? W0 : (mat == 1) ? W1 : W2) : W0;
    const float* bias = (MODE == 0) ? ((mat == 0) ? bias0 : (mat == 1) ? bias1 : bias2)
                                    : bias0;

    bias_s[tid] = bias[n0 + tid];

    float acc[4][8][4];
    #pragma unroll
    for (int i = 0; i < 4; i++)
        #pragma unroll
        for (int j = 0; j < 8; j++)
            #pragma unroll
            for (int c = 0; c < 4; c++) acc[i][j][c] = 0.f;

    // per-thread loader coordinates (8 float4 for A, 8 for B per chunk)
    float4 apf[8], bpf[8];

    #define LOAD_CHUNK(K0) do { \
        _Pragma("unroll") \
        for (int it = 0; it < 8; ++it) { \
            const int idx = it * 128 + tid; \
            apf[it] = *(const float4*)(A + (size_t)(m0 + (idx >> 3)) * EMB + (K0) + (idx & 7) * 4); \
            bpf[it] = *(const float4*)(W + (size_t)((K0) + (idx >> 5)) * EMB + n0 + (idx & 31) * 4); \
        } \
    } while (0)

    #define STORE_CHUNK(BUF) do { \
        uint32_t* Ab = As + (BUF) * ABUF; \
        uint32_t* Bb = Bs + (BUF) * BBUF; \
        _Pragma("unroll") \
        for (int it = 0; it < 8; ++it) { \
            const int idx = it * 128 + tid; \
            uint4 ta; \
            ta.x = f2tf32(apf[it].x); ta.y = f2tf32(apf[it].y); \
            ta.z = f2tf32(apf[it].z); ta.w = f2tf32(apf[it].w); \
            *(uint4*)&Ab[(idx >> 3) * APAD + (idx & 7) * 4] = ta; \
            uint4 tb; \
            tb.x = f2tf32(bpf[it].x); tb.y = f2tf32(bpf[it].y); \
            tb.z = f2tf32(bpf[it].z); tb.w = f2tf32(bpf[it].w); \
            *(uint4*)&Bb[(idx >> 5) * BPAD + (idx & 31) * 4] = tb; \
        } \
    } while (0)

    LOAD_CHUNK(0);
    STORE_CHUNK(0);
    __syncthreads();

    for (int c = 0; c < EMB / 32; ++c) {
        if (c < EMB / 32 - 1)
            LOAD_CHUNK((c + 1) * 32);

        const uint32_t* Ab = As + (c & 1) * ABUF;
        const uint32_t* Bb = Bs + (c & 1) * BBUF;

        #pragma unroll
        for (int ks = 0; ks < 4; ++ks) {
            const int kk = ks * 8 + qd;
            uint32_t af[4][4], bf[8][2];
            #pragma unroll
            for (int mt = 0; mt < 4; ++mt) {
                const int r = wm + mt * 16 + g;
                af[mt][0] = Ab[r * APAD + kk];
                af[mt][1] = Ab[(r + 8) * APAD + kk];
                af[mt][2] = Ab[r * APAD + kk + 4];
                af[mt][3] = Ab[(r + 8) * APAD + kk + 4];
            }
            #pragma unroll
            for (int nt = 0; nt < 8; ++nt) {
                const int n = wn + nt * 8 + g;
                bf[nt][0] = Bb[kk * BPAD + n];
                bf[nt][1] = Bb[(kk + 4) * BPAD + n];
            }
            #pragma unroll
            for (int mt = 0; mt < 4; ++mt)
                #pragma unroll
                for (int nt = 0; nt < 8; ++nt)
                    mma_tf32(acc[mt][nt], af[mt], bf[nt]);
        }

        if (c < EMB / 32 - 1)
            STORE_CHUNK((c + 1) & 1);
        __syncthreads();
    }

    #undef LOAD_CHUNK
    #undef STORE_CHUNK

    // ---------------- epilogue ----------------
    #pragma unroll
    for (int mt = 0; mt < 4; ++mt) {
        #pragma unroll
        for (int ci = 0; ci < 2; ++ci) {
            const int m = m0 + wm + mt * 16 + g + ci * 8;
            #pragma unroll
            for (int nt = 0; nt < 8; ++nt) {
                const int nl = wn + nt * 8 + qd * 2;
                const int n  = n0 + nl;
                float2 o;
                o.x = acc[mt][nt][ci * 2 + 0] + bias_s[nl];
                o.y = acc[mt][nt][ci * 2 + 1] + bias_s[nl + 1];
                if (MODE == 0) {
                    const int b = m >> 11;
                    const int t = m & (SEQ - 1);
                    const int h = n >> 6;
                    const int d = n & (HSZ - 1);
                    float* dst = (mat == 0) ? g_q : (mat == 1) ? g_k : g_v;
                    *(float2*)(dst + ((((size_t)b * NHEAD + h) * SEQ) + t) * HSZ + d) = o;
                } else {
                    *(float2*)(outp + (size_t)m * EMB + n) = o;
                }
            }
        }
    }
}

// =============================================================
// tensor-core causal flash attention (tf32 mma.sync) — unchanged.
// =============================================================
#define KSTRIDE 68
#define VSTRIDE 72
#define ATT_SMEM_BYTES ((64 * KSTRIDE + 64 * VSTRIDE + 4 * 16 * KSTRIDE) * 4)

__global__ __launch_bounds__(128) void attn_mma_kernel()
{
    extern __shared__ uint32_t sm[];
    uint32_t* Ks = sm;
    uint32_t* Vs = sm + 64 * KSTRIDE;
    const int tid  = threadIdx.x;
    const int wid  = tid >> 5;
    const int lane = tid & 31;
    const int g    = lane >> 2;
    const int qd   = lane & 3;
    uint32_t* Ps = sm + 64 * KSTRIDE + 64 * VSTRIDE + wid * 16 * KSTRIDE;

    const int bh = blockIdx.y;
    const int q0 = blockIdx.x * 64;
    const int wq = wid * 16;
    const size_t base = (size_t)bh * SEQ * HSZ;
    const float* Qp = g_q + base;
    const float* Kp = g_k + base;
    const float* Vp = g_v + base;

    #pragma unroll
    for (int it = 0; it < 8; ++it) {
        int idx = it * 128 + tid;
        int row = idx >> 4;
        int c4  = idx & 15;
        float4 v = *(const float4*)(Qp + (size_t)(q0 + row) * HSZ + c4 * 4);
        uint4 t;
        t.x = f2tf32(v.x * 0.125f); t.y = f2tf32(v.y * 0.125f);
        t.z = f2tf32(v.z * 0.125f); t.w = f2tf32(v.w * 0.125f);
        *(uint4*)&Ks[row * KSTRIDE + c4 * 4] = t;
    }
    __syncthreads();

    uint32_t qf[8][4];
    #pragma unroll
    for (int ks = 0; ks < 8; ++ks) {
        qf[ks][0] = Ks[(wq + g) * KSTRIDE + ks * 8 + qd];
        qf[ks][1] = Ks[(wq + g + 8) * KSTRIDE + ks * 8 + qd];
        qf[ks][2] = Ks[(wq + g) * KSTRIDE + ks * 8 + qd + 4];
        qf[ks][3] = Ks[(wq + g + 8) * KSTRIDE + ks * 8 + qd + 4];
    }
    __syncthreads();

    float of[8][4];
    #pragma unroll
    for (int nt = 0; nt < 8; ++nt)
        #pragma unroll
        for (int c = 0; c < 4; ++c) of[nt][c] = 0.f;
    float m0 = -1e30f, m1 = -1e30f, l0 = 0.f, l1 = 0.f;

    const int ntile = (q0 >> 6) + 1;
    for (int kt = 0; kt < ntile; ++kt) {
        const int kb = kt * 64;

        #pragma unroll
        for (int it = 0; it < 8; ++it) {
            int idx = it * 128 + tid;
            int row = idx >> 4;
            int c4  = idx & 15;
            float4 kv = *(const float4*)(Kp + (size_t)(kb + row) * HSZ + c4 * 4);
            uint4 tk;
            tk.x = f2tf32(kv.x); tk.y = f2tf32(kv.y);
            tk.z = f2tf32(kv.z); tk.w = f2tf32(kv.w);
            *(uint4*)&Ks[row * KSTRIDE + c4 * 4] = tk;
            float4 vv = *(const float4*)(Vp + (size_t)(kb + row) * HSZ + c4 * 4);
            uint4 tv;
            tv.x = f2tf32(vv.x); tv.y = f2tf32(vv.y);
            tv.z = f2tf32(vv.z); tv.w = f2tf32(vv.w);
            *(uint4*)&Vs[row * VSTRIDE + c4 * 4] = tv;
        }
        __syncthreads();

        float sf[8][4];
        #pragma unroll
        for (int nt = 0; nt < 8; ++nt) {
            float s4[4] = {0.f, 0.f, 0.f, 0.f};
            #pragma unroll
            for (int ks = 0; ks < 8; ++ks) {
                uint32_t bf[2];
                bf[0] = Ks[(nt * 8 + g) * KSTRIDE + ks * 8 + qd];
                bf[1] = Ks[(nt * 8 + g) * KSTRIDE + ks * 8 + qd + 4];
                mma_tf32(s4, qf[ks], bf);
            }
            if (kt == ntile - 1) {
                const int kl = nt * 8 + 2 * qd;
                if (kl     > wq + g)     s4[0] = -1e30f;
                if (kl + 1 > wq + g)     s4[1] = -1e30f;
                if (kl     > wq + g + 8) s4[2] = -1e30f;
                if (kl + 1 > wq + g + 8) s4[3] = -1e30f;
            }
            sf[nt][0] = s4[0]; sf[nt][1] = s4[1];
            sf[nt][2] = s4[2]; sf[nt][3] = s4[3];
        }

        float t0 = -1e30f, t1 = -1e30f;
        #pragma unroll
        for (int nt = 0; nt < 8; ++nt) {
            t0 = fmaxf(t0, fmaxf(sf[nt][0], sf[nt][1]));
            t1 = fmaxf(t1, fmaxf(sf[nt][2], sf[nt][3]));
        }
        t0 = fmaxf(t0, __shfl_xor_sync(0xffffffffu, t0, 1));
        t0 = fmaxf(t0, __shfl_xor_sync(0xffffffffu, t0, 2));
        t1 = fmaxf(t1, __shfl_xor_sync(0xffffffffu, t1, 1));
        t1 = fmaxf(t1, __shfl_xor_sync(0xffffffffu, t1, 2));

        const float mn0 = fmaxf(m0, t0);
        const float mn1 = fmaxf(m1, t1);
        const float cr0 = __expf(m0 - mn0);
        const float cr1 = __expf(m1 - mn1);
        m0 = mn0; m1 = mn1;

        float ps0 = 0.f, ps1 = 0.f;
        #pragma unroll
        for (int nt = 0; nt < 8; ++nt) {
            sf[nt][0] = __expf(sf[nt][0] - mn0);
            sf[nt][1] = __expf(sf[nt][1] - mn0);
            sf[nt][2] = __expf(sf[nt][2] - mn1);
            sf[nt][3] = __expf(sf[nt][3] - mn1);
            ps0 += sf[nt][0] + sf[nt][1];
            ps1 += sf[nt][2] + sf[nt][3];
        }
        ps0 += __shfl_xor_sync(0xffffffffu, ps0, 1);
        ps0 += __shfl_xor_sync(0xffffffffu, ps0, 2);
        ps1 += __shfl_xor_sync(0xffffffffu, ps1, 1);
        ps1 += __shfl_xor_sync(0xffffffffu, ps1, 2);
        l0 = l0 * cr0 + ps0;
        l1 = l1 * cr1 + ps1;

        #pragma unroll
        for (int nt = 0; nt < 8; ++nt) {
            of[nt][0] *= cr0; of[nt][1] *= cr0;
            of[nt][2] *= cr1; of[nt][3] *= cr1;
        }

        #pragma unroll
        for (int nt = 0; nt < 8; ++nt) {
            uint2 p0, p1;
            p0.x = f2tf32(sf[nt][0]); p0.y = f2tf32(sf[nt][1]);
            p1.x = f2tf32(sf[nt][2]); p1.y = f2tf32(sf[nt][3]);
            *(uint2*)&Ps[g * KSTRIDE + nt * 8 + 2 * qd] = p0;
            *(uint2*)&Ps[(g + 8) * KSTRIDE + nt * 8 + 2 * qd] = p1;
        }
        __syncwarp();

        #pragma unroll
        for (int ks = 0; ks < 8; ++ks) {
            uint32_t af[4];
            af[0] = Ps[g * KSTRIDE + ks * 8 + qd];
            af[1] = Ps[(g + 8) * KSTRIDE + ks * 8 + qd];
            af[2] = Ps[g * KSTRIDE + ks * 8 + qd + 4];
            af[3] = Ps[(g + 8) * KSTRIDE + ks * 8 + qd + 4];
            #pragma unroll
            for (int nt = 0; nt < 8; ++nt) {
                uint32_t bf[2];
                bf[0] = Vs[(ks * 8 + qd) * VSTRIDE + nt * 8 + g];
                bf[1] = Vs[(ks * 8 + qd + 4) * VSTRIDE + nt * 8 + g];
                mma_tf32(of[nt], af, bf);
            }
        }
        __syncthreads();
    }

    const float inv0 = 1.f / l0;
    const float inv1 = 1.f / l1;
    const int b = bh / NHEAD;
    const int h = bh % NHEAD;
    const int r0 = q0 + wq + g;
    float* y0 = g_y + ((size_t)b * SEQ + r0) * EMB + h * HSZ;
    float* y1 = g_y + ((size_t)b * SEQ + r0 + 8) * EMB + h * HSZ;
    #pragma unroll
    for (int nt = 0; nt < 8; ++nt) {
        float2 o0, o1;
        o0.x = of[nt][0] * inv0; o0.y = of[nt][1] * inv0;
        o1.x = of[nt][2] * inv1; o1.y = of[nt][3] * inv1;
        *(float2*)(y0 + nt * 8 + 2 * qd) = o0;
        *(float2*)(y1 + nt * 8 + 2 * qd) = o1;
    }
}

// =============================================================
extern "C" void kernel_launch(void* const* d_in, const int* in_sizes, int n_in,
                              void* d_out, int out_size)
{
    const float* x  = (const float*)d_in[0];
    const float* Wq = (const float*)d_in[1];
    const float* bq = (const float*)d_in[2];
    const float* Wk = (const float*)d_in[3];
    const float* bk = (const float*)d_in[4];
    const float* Wv = (const float*)d_in[5];
    const float* bv = (const float*)d_in[6];
    const float* Wo = (const float*)d_in[7];
    const float* bo = (const float*)d_in[8];
    float* out = (float*)d_out;

    cudaFuncSetAttribute(gemm_kernel<0>, cudaFuncAttributeMaxDynamicSharedMemorySize,
                         GEMM_SMEM_BYTES);
    cudaFuncSetAttribute(gemm_kernel<1>, cudaFuncAttributeMaxDynamicSharedMemorySize,
                         GEMM_SMEM_BYTES);
    cudaFuncSetAttribute(attn_mma_kernel, cudaFuncAttributeMaxDynamicSharedMemorySize,
                         ATT_SMEM_BYTES);

    dim3 qkv_grid(EMB / 128, MTOT / 128, 3);
    gemm_kernel<0><<<qkv_grid, 128, GEMM_SMEM_BYTES>>>(x, Wq, Wk, Wv, bq, bk, bv, nullptr);

    dim3 attn_grid(SEQ / 64, BATCH * NHEAD);
    attn_mma_kernel<<<attn_grid, 128, ATT_SMEM_BYTES>>>();

    dim3 oproj_grid(EMB / 128, MTOT / 128);
    gemm_kernel<1><<<oproj_grid, 128, GEMM_SMEM_BYTES>>>(nullptr, Wo, nullptr, nullptr, bo, nullptr, nullptr, out);
}

// round 8
// speedup vs baseline: 4.5337x; 1.1038x over previous
#include <cuda_runtime.h>
#include <cuda_bf16.h>
#include <cstdint>
#include <math.h>

// ---------------- problem dims ----------------
#define BATCH 4
#define SEQ   2048
#define EMB   1024
#define NHEAD 16
#define HSZ   64
#define MTOT  (BATCH * SEQ)   // 8192

// ---------------- device scratch (no runtime allocation) ----------------
// All tf32-bit (u32) tensors. q pre-scaled by 1/8.
__device__ __align__(128) uint32_t g_q[(size_t)BATCH * NHEAD * SEQ * HSZ];
__device__ __align__(128) uint32_t g_k[(size_t)BATCH * NHEAD * SEQ * HSZ];
__device__ __align__(128) uint32_t g_v[(size_t)BATCH * NHEAD * SEQ * HSZ];
__device__ __align__(128) uint32_t g_y[(size_t)MTOT * EMB];
__device__ __align__(128) uint32_t g_xt[(size_t)MTOT * EMB];
__device__ __align__(128) uint32_t g_wt[(size_t)4 * EMB * EMB];

// ---------------- helpers ----------------
__device__ __forceinline__ uint32_t f2tf32(float f) {
    uint32_t r;
    asm("cvt.rna.tf32.f32 %0, %1;" : "=r"(r) : "f"(f));
    return r;
}

__device__ __forceinline__ void mma_tf32(float* d, const uint32_t* a, const uint32_t* b) {
    asm volatile(
        "mma.sync.aligned.m16n8k8.row.col.f32.tf32.tf32.f32 "
        "{%0,%1,%2,%3}, {%4,%5,%6,%7}, {%8,%9}, {%0,%1,%2,%3};"
        : "+f"(d[0]), "+f"(d[1]), "+f"(d[2]), "+f"(d[3])
        : "r"(a[0]), "r"(a[1]), "r"(a[2]), "r"(a[3]), "r"(b[0]), "r"(b[1]));
}

__device__ __forceinline__ void cp16(uint32_t sdst, const void* gsrc) {
    asm volatile("cp.async.cg.shared.global [%0], [%1], 16;" :: "r"(sdst), "l"(gsrc));
}
__device__ __forceinline__ void cp_commit() {
    asm volatile("cp.async.commit_group;" ::: "memory");
}
template <int N>
__device__ __forceinline__ void cp_wait() {
    asm volatile("cp.async.wait_group %0;" :: "n"(N) : "memory");
}

// =============================================================
// converters: fp32 -> tf32 bits.  NOTE: device globals referenced from
// device code only (never passed as host-side kernel args).
// =============================================================
__global__ __launch_bounds__(256) void convert_x_kernel(const float* __restrict__ src)
{
    const size_t i = ((size_t)blockIdx.x * 256 + threadIdx.x) * 4;
    float4 v = *(const float4*)(src + i);
    uint4 t;
    t.x = f2tf32(v.x); t.y = f2tf32(v.y); t.z = f2tf32(v.z); t.w = f2tf32(v.w);
    *(uint4*)(g_xt + i) = t;
}

__global__ __launch_bounds__(256) void convert_w_kernel(
    const float* __restrict__ W0, const float* __restrict__ W1,
    const float* __restrict__ W2, const float* __restrict__ W3)
{
    const int mat = blockIdx.z;
    const float* src = (mat == 0) ? W0 : (mat == 1) ? W1 : (mat == 2) ? W2 : W3;
    uint32_t* dst = g_wt + (size_t)mat * EMB * EMB;
    const size_t i = ((size_t)blockIdx.x * 256 + threadIdx.x) * 4;
    float4 v = *(const float4*)(src + i);
    uint4 t;
    t.x = f2tf32(v.x); t.y = f2tf32(v.y); t.z = f2tf32(v.z); t.w = f2tf32(v.w);
    *(uint4*)(dst + i) = t;
}

// ---------------- GEMM config ----------------
#define APAD 36
#define BPAD 136
#define ABUF (128 * APAD)   // words
#define BBUF (32 * BPAD)
#define GEMM_SMEM_BYTES ((2 * ABUF + 2 * BBUF + 128) * 4)

// =============================================================
// tf32 mma.sync GEMM, cp.async pipelined. Inputs are tf32 bits.
// MODE 0: qkv (blockIdx.z = matrix; scatter tf32 bits to [B,H,T,HS], q scaled)
// MODE 1: output projection (A = g_y; writes fp32 d_out)
// =============================================================
template <int MODE>
__global__ __launch_bounds__(128) void gemm_kernel(
    const float* __restrict__ bias0, const float* __restrict__ bias1,
    const float* __restrict__ bias2, float* __restrict__ outp)
{
    extern __shared__ uint32_t dynsm[];
    uint32_t* As = dynsm;                       // [2][ABUF]
    uint32_t* Bs = dynsm + 2 * ABUF;            // [2][BBUF]
    float* bias_s = (float*)(dynsm + 2 * ABUF + 2 * BBUF);

    const int tid  = threadIdx.x;
    const int wid  = tid >> 5;
    const int lane = tid & 31;
    const int g    = lane >> 2;
    const int qd   = lane & 3;
    const int wm   = (wid >> 1) * 64;
    const int wn   = (wid & 1) * 64;
    const int n0   = blockIdx.x * 128;
    const int m0   = blockIdx.y * 128;
    const int mat  = (MODE == 0) ? (int)blockIdx.z : 3;

    const uint32_t* A = (MODE == 0) ? g_xt : g_y;
    const uint32_t* W = g_wt + (size_t)mat * EMB * EMB;
    const float* bias = (MODE == 0) ? ((mat == 0) ? bias0 : (mat == 1) ? bias1 : bias2)
                                    : bias0;

    bias_s[tid] = bias[n0 + tid];

    const uint32_t sA = (uint32_t)__cvta_generic_to_shared(As);
    const uint32_t sB = (uint32_t)__cvta_generic_to_shared(Bs);

    const int a_row = tid >> 3;
    const int a_kq  = tid & 7;
    const int b_kr  = tid >> 5;
    const int b_nq  = tid & 31;

    #define ISSUE_CHUNK(K0, BUF) do { \
        const uint32_t sAb = sA + (BUF) * (ABUF * 4); \
        const uint32_t sBb = sB + (BUF) * (BBUF * 4); \
        _Pragma("unroll") \
        for (int it = 0; it < 8; ++it) { \
            const int ar = it * 16 + a_row; \
            cp16(sAb + (ar * APAD + a_kq * 4) * 4, \
                 A + (size_t)(m0 + ar) * EMB + (K0) + a_kq * 4); \
            const int br = it * 4 + b_kr; \
            cp16(sBb + (br * BPAD + b_nq * 4) * 4, \
                 W + (size_t)((K0) + br) * EMB + n0 + b_nq * 4); \
        } \
    } while (0)

    float acc[4][8][4];
    #pragma unroll
    for (int i = 0; i < 4; i++)
        #pragma unroll
        for (int j = 0; j < 8; j++)
            #pragma unroll
            for (int c = 0; c < 4; c++) acc[i][j][c] = 0.f;

    ISSUE_CHUNK(0, 0);
    cp_commit();

    for (int c = 0; c < EMB / 32; ++c) {
        if (c + 1 < EMB / 32) {
            ISSUE_CHUNK((c + 1) * 32, (c + 1) & 1);
            cp_commit();
        }
        if (c + 1 < EMB / 32) cp_wait<1>(); else cp_wait<0>();
        __syncthreads();

        const uint32_t* Ab = As + (c & 1) * ABUF;
        const uint32_t* Bb = Bs + (c & 1) * BBUF;

        #pragma unroll
        for (int ks = 0; ks < 4; ++ks) {
            const int kk = ks * 8 + qd;
            uint32_t af[4][4], bf[8][2];
            #pragma unroll
            for (int mt = 0; mt < 4; ++mt) {
                const int r = wm + mt * 16 + g;
                af[mt][0] = Ab[r * APAD + kk];
                af[mt][1] = Ab[(r + 8) * APAD + kk];
                af[mt][2] = Ab[r * APAD + kk + 4];
                af[mt][3] = Ab[(r + 8) * APAD + kk + 4];
            }
            #pragma unroll
            for (int nt = 0; nt < 8; ++nt) {
                const int n = wn + nt * 8 + g;
                bf[nt][0] = Bb[kk * BPAD + n];
                bf[nt][1] = Bb[(kk + 4) * BPAD + n];
            }
            #pragma unroll
            for (int mt = 0; mt < 4; ++mt)
                #pragma unroll
                for (int nt = 0; nt < 8; ++nt)
                    mma_tf32(acc[mt][nt], af[mt], bf[nt]);
        }
        __syncthreads();
    }
    #undef ISSUE_CHUNK

    // ---------------- epilogue ----------------
    #pragma unroll
    for (int mt = 0; mt < 4; ++mt) {
        #pragma unroll
        for (int ci = 0; ci < 2; ++ci) {
            const int m = m0 + wm + mt * 16 + g + ci * 8;
            #pragma unroll
            for (int nt = 0; nt < 8; ++nt) {
                const int nl = wn + nt * 8 + qd * 2;
                const int n  = n0 + nl;
                float vx = acc[mt][nt][ci * 2 + 0] + bias_s[nl];
                float vy = acc[mt][nt][ci * 2 + 1] + bias_s[nl + 1];
                if (MODE == 0) {
                    if (mat == 0) { vx *= 0.125f; vy *= 0.125f; }
                    const int b = m >> 11;
                    const int t = m & (SEQ - 1);
                    const int h = n >> 6;
                    const int d = n & (HSZ - 1);
                    uint32_t* dst = (mat == 0) ? g_q : (mat == 1) ? g_k : g_v;
                    uint2 o;
                    o.x = f2tf32(vx); o.y = f2tf32(vy);
                    *(uint2*)(dst + ((((size_t)b * NHEAD + h) * SEQ) + t) * HSZ + d) = o;
                } else {
                    float2 o; o.x = vx; o.y = vy;
                    *(float2*)(outp + (size_t)m * EMB + n) = o;
                }
            }
        }
    }
}

// =============================================================
// tensor-core causal flash attention, cp.async double-buffered K/V.
// =============================================================
#define KSTRIDE 68
#define VSTRIDE 72
#define KVBUF_K (64 * KSTRIDE)
#define KVBUF_V (64 * VSTRIDE)
#define ATT_SMEM_BYTES ((2 * KVBUF_K + 2 * KVBUF_V + 64 * KSTRIDE) * 4)   // 89088

__global__ __launch_bounds__(128) void attn_mma_kernel()
{
    extern __shared__ uint32_t sm[];
    uint32_t* KsBase = sm;                               // [2][64*KSTRIDE]
    uint32_t* VsBase = sm + 2 * KVBUF_K;                 // [2][64*VSTRIDE]
    uint32_t* Psall  = sm + 2 * KVBUF_K + 2 * KVBUF_V;   // [64][KSTRIDE]
    const int tid  = threadIdx.x;
    const int wid  = tid >> 5;
    const int lane = tid & 31;
    const int g    = lane >> 2;
    const int qd   = lane & 3;
    uint32_t* Ps = Psall + wid * 16 * KSTRIDE;

    const int bh = blockIdx.y;
    const int q0 = blockIdx.x * 64;
    const int wq = wid * 16;
    const size_t base = (size_t)bh * SEQ * HSZ;
    const uint32_t* Qp = g_q + base;
    const uint32_t* Kp = g_k + base;
    const uint32_t* Vp = g_v + base;

    const uint32_t sK = (uint32_t)__cvta_generic_to_shared(KsBase);
    const uint32_t sV = (uint32_t)__cvta_generic_to_shared(VsBase);

    const int l_row = tid >> 4;
    const int l_c4  = tid & 15;

    #define ISSUE_TILE(KB, BUF) do { \
        const uint32_t sKb = sK + (BUF) * (KVBUF_K * 4); \
        const uint32_t sVb = sV + (BUF) * (KVBUF_V * 4); \
        _Pragma("unroll") \
        for (int it = 0; it < 8; ++it) { \
            const int row = it * 8 + l_row; \
            cp16(sKb + (row * KSTRIDE + l_c4 * 4) * 4, \
                 Kp + (size_t)((KB) + row) * HSZ + l_c4 * 4); \
            cp16(sVb + (row * VSTRIDE + l_c4 * 4) * 4, \
                 Vp + (size_t)((KB) + row) * HSZ + l_c4 * 4); \
        } \
    } while (0)

    ISSUE_TILE(0, 0);
    cp_commit();

    // ---- stage Q (pre-scaled tf32 bits) through Ps area ----
    #pragma unroll
    for (int it = 0; it < 8; ++it) {
        const int row = it * 8 + l_row;
        *(uint4*)&Psall[row * KSTRIDE + l_c4 * 4] =
            *(const uint4*)(Qp + (size_t)(q0 + row) * HSZ + l_c4 * 4);
    }
    __syncthreads();

    uint32_t qf[8][4];
    #pragma unroll
    for (int ks = 0; ks < 8; ++ks) {
        qf[ks][0] = Psall[(wq + g) * KSTRIDE + ks * 8 + qd];
        qf[ks][1] = Psall[(wq + g + 8) * KSTRIDE + ks * 8 + qd];
        qf[ks][2] = Psall[(wq + g) * KSTRIDE + ks * 8 + qd + 4];
        qf[ks][3] = Psall[(wq + g + 8) * KSTRIDE + ks * 8 + qd + 4];
    }

    float of[8][4];
    #pragma unroll
    for (int nt = 0; nt < 8; ++nt)
        #pragma unroll
        for (int c = 0; c < 4; ++c) of[nt][c] = 0.f;
    float m0 = -1e30f, m1 = -1e30f, l0 = 0.f, l1 = 0.f;

    const int ntile = (q0 >> 6) + 1;
    for (int kt = 0; kt < ntile; ++kt) {
        if (kt + 1 < ntile) {
            ISSUE_TILE((kt + 1) * 64, (kt + 1) & 1);
            cp_commit();
        }
        if (kt + 1 < ntile) cp_wait<1>(); else cp_wait<0>();
        __syncthreads();

        const uint32_t* Ks = KsBase + (kt & 1) * KVBUF_K;
        const uint32_t* Vs = VsBase + (kt & 1) * KVBUF_V;

        // ---- S = Q K^T ----
        float sf[8][4];
        #pragma unroll
        for (int nt = 0; nt < 8; ++nt) {
            float s4[4] = {0.f, 0.f, 0.f, 0.f};
            #pragma unroll
            for (int ks = 0; ks < 8; ++ks) {
                uint32_t bf[2];
                bf[0] = Ks[(nt * 8 + g) * KSTRIDE + ks * 8 + qd];
                bf[1] = Ks[(nt * 8 + g) * KSTRIDE + ks * 8 + qd + 4];
                mma_tf32(s4, qf[ks], bf);
            }
            if (kt == ntile - 1) {
                const int kl = nt * 8 + 2 * qd;
                if (kl     > wq + g)     s4[0] = -1e30f;
                if (kl + 1 > wq + g)     s4[1] = -1e30f;
                if (kl     > wq + g + 8) s4[2] = -1e30f;
                if (kl + 1 > wq + g + 8) s4[3] = -1e30f;
            }
            sf[nt][0] = s4[0]; sf[nt][1] = s4[1];
            sf[nt][2] = s4[2]; sf[nt][3] = s4[3];
        }

        // ---- online softmax ----
        float t0 = -1e30f, t1 = -1e30f;
        #pragma unroll
        for (int nt = 0; nt < 8; ++nt) {
            t0 = fmaxf(t0, fmaxf(sf[nt][0], sf[nt][1]));
            t1 = fmaxf(t1, fmaxf(sf[nt][2], sf[nt][3]));
        }
        t0 = fmaxf(t0, __shfl_xor_sync(0xffffffffu, t0, 1));
        t0 = fmaxf(t0, __shfl_xor_sync(0xffffffffu, t0, 2));
        t1 = fmaxf(t1, __shfl_xor_sync(0xffffffffu, t1, 1));
        t1 = fmaxf(t1, __shfl_xor_sync(0xffffffffu, t1, 2));

        const float mn0 = fmaxf(m0, t0);
        const float mn1 = fmaxf(m1, t1);
        const float cr0 = __expf(m0 - mn0);
        const float cr1 = __expf(m1 - mn1);
        m0 = mn0; m1 = mn1;

        float ps0 = 0.f, ps1 = 0.f;
        #pragma unroll
        for (int nt = 0; nt < 8; ++nt) {
            sf[nt][0] = __expf(sf[nt][0] - mn0);
            sf[nt][1] = __expf(sf[nt][1] - mn0);
            sf[nt][2] = __expf(sf[nt][2] - mn1);
            sf[nt][3] = __expf(sf[nt][3] - mn1);
            ps0 += sf[nt][0] + sf[nt][1];
            ps1 += sf[nt][2] + sf[nt][3];
        }
        ps0 += __shfl_xor_sync(0xffffffffu, ps0, 1);
        ps0 += __shfl_xor_sync(0xffffffffu, ps0, 2);
        ps1 += __shfl_xor_sync(0xffffffffu, ps1, 1);
        ps1 += __shfl_xor_sync(0xffffffffu, ps1, 2);
        l0 = l0 * cr0 + ps0;
        l1 = l1 * cr1 + ps1;

        #pragma unroll
        for (int nt = 0; nt < 8; ++nt) {
            of[nt][0] *= cr0; of[nt][1] *= cr0;
            of[nt][2] *= cr1; of[nt][3] *= cr1;
        }

        // ---- P (tf32) to per-warp smem ----
        #pragma unroll
        for (int nt = 0; nt < 8; ++nt) {
            uint2 p0, p1;
            p0.x = f2tf32(sf[nt][0]); p0.y = f2tf32(sf[nt][1]);
            p1.x = f2tf32(sf[nt][2]); p1.y = f2tf32(sf[nt][3]);
            *(uint2*)&Ps[g * KSTRIDE + nt * 8 + 2 * qd] = p0;
            *(uint2*)&Ps[(g + 8) * KSTRIDE + nt * 8 + 2 * qd] = p1;
        }
        __syncwarp();

        // ---- O += P V ----
        #pragma unroll
        for (int ks = 0; ks < 8; ++ks) {
            uint32_t af[4];
            af[0] = Ps[g * KSTRIDE + ks * 8 + qd];
            af[1] = Ps[(g + 8) * KSTRIDE + ks * 8 + qd];
            af[2] = Ps[g * KSTRIDE + ks * 8 + qd + 4];
            af[3] = Ps[(g + 8) * KSTRIDE + ks * 8 + qd + 4];
            #pragma unroll
            for (int nt = 0; nt < 8; ++nt) {
                uint32_t bf[2];
                bf[0] = Vs[(ks * 8 + qd) * VSTRIDE + nt * 8 + g];
                bf[1] = Vs[(ks * 8 + qd + 4) * VSTRIDE + nt * 8 + g];
                mma_tf32(of[nt], af, bf);
            }
        }
        __syncthreads();
    }
    #undef ISSUE_TILE

    // ---- epilogue: normalize, write y (tf32 bits, [B,T,C]) ----
    const float inv0 = 1.f / l0;
    const float inv1 = 1.f / l1;
    const int b = bh / NHEAD;
    const int h = bh % NHEAD;
    const int r0 = q0 + wq + g;
    uint32_t* y0 = g_y + ((size_t)b * SEQ + r0) * EMB + h * HSZ;
    uint32_t* y1 = g_y + ((size_t)b * SEQ + r0 + 8) * EMB + h * HSZ;
    #pragma unroll
    for (int nt = 0; nt < 8; ++nt) {
        uint2 o0, o1;
        o0.x = f2tf32(of[nt][0] * inv0); o0.y = f2tf32(of[nt][1] * inv0);
        o1.x = f2tf32(of[nt][2] * inv1); o1.y = f2tf32(of[nt][3] * inv1);
        *(uint2*)(y0 + nt * 8 + 2 * qd) = o0;
        *(uint2*)(y1 + nt * 8 + 2 * qd) = o1;
    }
}

// =============================================================
extern "C" void kernel_launch(void* const* d_in, const int* in_sizes, int n_in,
                              void* d_out, int out_size)
{
    const float* x  = (const float*)d_in[0];
    const float* Wq = (const float*)d_in[1];
    const float* bq = (const float*)d_in[2];
    const float* Wk = (const float*)d_in[3];
    const float* bk = (const float*)d_in[4];
    const float* Wv = (const float*)d_in[5];
    const float* bv = (const float*)d_in[6];
    const float* Wo = (const float*)d_in[7];
    const float* bo = (const float*)d_in[8];
    float* out = (float*)d_out;

    cudaFuncSetAttribute(gemm_kernel<0>, cudaFuncAttributeMaxDynamicSharedMemorySize,
                         GEMM_SMEM_BYTES);
    cudaFuncSetAttribute(gemm_kernel<1>, cudaFuncAttributeMaxDynamicSharedMemorySize,
                         GEMM_SMEM_BYTES);
    cudaFuncSetAttribute(attn_mma_kernel, cudaFuncAttributeMaxDynamicSharedMemorySize,
                         ATT_SMEM_BYTES);

    convert_x_kernel<<<(MTOT * EMB / 4) / 256, 256>>>(x);
    convert_w_kernel<<<dim3((EMB * EMB / 4) / 256, 1, 4), 256>>>(Wq, Wk, Wv, Wo);

    dim3 qkv_grid(EMB / 128, MTOT / 128, 3);
    gemm_kernel<0><<<qkv_grid, 128, GEMM_SMEM_BYTES>>>(bq, bk, bv, nullptr);

    dim3 attn_grid(SEQ / 64, BATCH * NHEAD);
    attn_mma_kernel<<<attn_grid, 128, ATT_SMEM_BYTES>>>();

    dim3 oproj_grid(EMB / 128, MTOT / 128);
    gemm_kernel<1><<<oproj_grid, 128, GEMM_SMEM_BYTES>>>(bo, nullptr, nullptr, out);
}

// round 9
// speedup vs baseline: 4.5564x; 1.0050x over previous
#include <cuda_runtime.h>
#include <cuda_bf16.h>
#include <cstdint>
#include <math.h>

// ---------------- problem dims ----------------
#define BATCH 4
#define SEQ   2048
#define EMB   1024
#define NHEAD 16
#define HSZ   64
#define MTOT  (BATCH * SEQ)   // 8192

// ---------------- device scratch (no runtime allocation) ----------------
// All tf32-bit (u32) tensors. q pre-scaled by 1/8.
__device__ __align__(128) uint32_t g_q[(size_t)BATCH * NHEAD * SEQ * HSZ];
__device__ __align__(128) uint32_t g_k[(size_t)BATCH * NHEAD * SEQ * HSZ];
__device__ __align__(128) uint32_t g_v[(size_t)BATCH * NHEAD * SEQ * HSZ];
__device__ __align__(128) uint32_t g_y[(size_t)MTOT * EMB];
__device__ __align__(128) uint32_t g_xt[(size_t)MTOT * EMB];
__device__ __align__(128) uint32_t g_wt[(size_t)4 * EMB * EMB];

// ---------------- helpers ----------------
__device__ __forceinline__ uint32_t f2tf32(float f) {
    uint32_t r;
    asm("cvt.rna.tf32.f32 %0, %1;" : "=r"(r) : "f"(f));
    return r;
}

__device__ __forceinline__ void mma_tf32(float* d, const uint32_t* a, const uint32_t* b) {
    asm volatile(
        "mma.sync.aligned.m16n8k8.row.col.f32.tf32.tf32.f32 "
        "{%0,%1,%2,%3}, {%4,%5,%6,%7}, {%8,%9}, {%0,%1,%2,%3};"
        : "+f"(d[0]), "+f"(d[1]), "+f"(d[2]), "+f"(d[3])
        : "r"(a[0]), "r"(a[1]), "r"(a[2]), "r"(a[3]), "r"(b[0]), "r"(b[1]));
}

__device__ __forceinline__ void cp16(uint32_t sdst, const void* gsrc) {
    asm volatile("cp.async.cg.shared.global [%0], [%1], 16;" :: "r"(sdst), "l"(gsrc));
}
__device__ __forceinline__ void cp_commit() {
    asm volatile("cp.async.commit_group;" ::: "memory");
}
template <int N>
__device__ __forceinline__ void cp_wait() {
    asm volatile("cp.async.wait_group %0;" :: "n"(N) : "memory");
}

// =============================================================
// converters: fp32 -> tf32 bits (device globals referenced in device code only)
// =============================================================
__global__ __launch_bounds__(256) void convert_x_kernel(const float* __restrict__ src)
{
    const size_t i = ((size_t)blockIdx.x * 256 + threadIdx.x) * 4;
    float4 v = *(const float4*)(src + i);
    uint4 t;
    t.x = f2tf32(v.x); t.y = f2tf32(v.y); t.z = f2tf32(v.z); t.w = f2tf32(v.w);
    *(uint4*)(g_xt + i) = t;
}

__global__ __launch_bounds__(256) void convert_w_kernel(
    const float* __restrict__ W0, const float* __restrict__ W1,
    const float* __restrict__ W2, const float* __restrict__ W3)
{
    const int mat = blockIdx.z;
    const float* src = (mat == 0) ? W0 : (mat == 1) ? W1 : (mat == 2) ? W2 : W3;
    uint32_t* dst = g_wt + (size_t)mat * EMB * EMB;
    const size_t i = ((size_t)blockIdx.x * 256 + threadIdx.x) * 4;
    float4 v = *(const float4*)(src + i);
    uint4 t;
    t.x = f2tf32(v.x); t.y = f2tf32(v.y); t.z = f2tf32(v.z); t.w = f2tf32(v.w);
    *(uint4*)(dst + i) = t;
}

// ---------------- GEMM config (unchanged from round 8) ----------------
#define APAD 36
#define BPAD 136
#define ABUF (128 * APAD)
#define BBUF (32 * BPAD)
#define GEMM_SMEM_BYTES ((2 * ABUF + 2 * BBUF + 128) * 4)

template <int MODE>
__global__ __launch_bounds__(128) void gemm_kernel(
    const float* __restrict__ bias0, const float* __restrict__ bias1,
    const float* __restrict__ bias2, float* __restrict__ outp)
{
    extern __shared__ uint32_t dynsm[];
    uint32_t* As = dynsm;
    uint32_t* Bs = dynsm + 2 * ABUF;
    float* bias_s = (float*)(dynsm + 2 * ABUF + 2 * BBUF);

    const int tid  = threadIdx.x;
    const int wid  = tid >> 5;
    const int lane = tid & 31;
    const int g    = lane >> 2;
    const int qd   = lane & 3;
    const int wm   = (wid >> 1) * 64;
    const int wn   = (wid & 1) * 64;
    const int n0   = blockIdx.x * 128;
    const int m0   = blockIdx.y * 128;
    const int mat  = (MODE == 0) ? (int)blockIdx.z : 3;

    const uint32_t* A = (MODE == 0) ? g_xt : g_y;
    const uint32_t* W = g_wt + (size_t)mat * EMB * EMB;
    const float* bias = (MODE == 0) ? ((mat == 0) ? bias0 : (mat == 1) ? bias1 : bias2)
                                    : bias0;

    bias_s[tid] = bias[n0 + tid];

    const uint32_t sA = (uint32_t)__cvta_generic_to_shared(As);
    const uint32_t sB = (uint32_t)__cvta_generic_to_shared(Bs);

    const int a_row = tid >> 3;
    const int a_kq  = tid & 7;
    const int b_kr  = tid >> 5;
    const int b_nq  = tid & 31;

    #define ISSUE_CHUNK(K0, BUF) do { \
        const uint32_t sAb = sA + (BUF) * (ABUF * 4); \
        const uint32_t sBb = sB + (BUF) * (BBUF * 4); \
        _Pragma("unroll") \
        for (int it = 0; it < 8; ++it) { \
            const int ar = it * 16 + a_row; \
            cp16(sAb + (ar * APAD + a_kq * 4) * 4, \
                 A + (size_t)(m0 + ar) * EMB + (K0) + a_kq * 4); \
            const int br = it * 4 + b_kr; \
            cp16(sBb + (br * BPAD + b_nq * 4) * 4, \
                 W + (size_t)((K0) + br) * EMB + n0 + b_nq * 4); \
        } \
    } while (0)

    float acc[4][8][4];
    #pragma unroll
    for (int i = 0; i < 4; i++)
        #pragma unroll
        for (int j = 0; j < 8; j++)
            #pragma unroll
            for (int c = 0; c < 4; c++) acc[i][j][c] = 0.f;

    ISSUE_CHUNK(0, 0);
    cp_commit();

    for (int c = 0; c < EMB / 32; ++c) {
        if (c + 1 < EMB / 32) {
            ISSUE_CHUNK((c + 1) * 32, (c + 1) & 1);
            cp_commit();
        }
        if (c + 1 < EMB / 32) cp_wait<1>(); else cp_wait<0>();
        __syncthreads();

        const uint32_t* Ab = As + (c & 1) * ABUF;
        const uint32_t* Bb = Bs + (c & 1) * BBUF;

        #pragma unroll
        for (int ks = 0; ks < 4; ++ks) {
            const int kk = ks * 8 + qd;
            uint32_t af[4][4], bf[8][2];
            #pragma unroll
            for (int mt = 0; mt < 4; ++mt) {
                const int r = wm + mt * 16 + g;
                af[mt][0] = Ab[r * APAD + kk];
                af[mt][1] = Ab[(r + 8) * APAD + kk];
                af[mt][2] = Ab[r * APAD + kk + 4];
                af[mt][3] = Ab[(r + 8) * APAD + kk + 4];
            }
            #pragma unroll
            for (int nt = 0; nt < 8; ++nt) {
                const int n = wn + nt * 8 + g;
                bf[nt][0] = Bb[kk * BPAD + n];
                bf[nt][1] = Bb[(kk + 4) * BPAD + n];
            }
            #pragma unroll
            for (int mt = 0; mt < 4; ++mt)
                #pragma unroll
                for (int nt = 0; nt < 8; ++nt)
                    mma_tf32(acc[mt][nt], af[mt], bf[nt]);
        }
        __syncthreads();
    }
    #undef ISSUE_CHUNK

    #pragma unroll
    for (int mt = 0; mt < 4; ++mt) {
        #pragma unroll
        for (int ci = 0; ci < 2; ++ci) {
            const int m = m0 + wm + mt * 16 + g + ci * 8;
            #pragma unroll
            for (int nt = 0; nt < 8; ++nt) {
                const int nl = wn + nt * 8 + qd * 2;
                const int n  = n0 + nl;
                float vx = acc[mt][nt][ci * 2 + 0] + bias_s[nl];
                float vy = acc[mt][nt][ci * 2 + 1] + bias_s[nl + 1];
                if (MODE == 0) {
                    if (mat == 0) { vx *= 0.125f; vy *= 0.125f; }
                    const int b = m >> 11;
                    const int t = m & (SEQ - 1);
                    const int h = n >> 6;
                    const int d = n & (HSZ - 1);
                    uint32_t* dst = (mat == 0) ? g_q : (mat == 1) ? g_k : g_v;
                    uint2 o;
                    o.x = f2tf32(vx); o.y = f2tf32(vy);
                    *(uint2*)(dst + ((((size_t)b * NHEAD + h) * SEQ) + t) * HSZ + d) = o;
                } else {
                    float2 o; o.x = vx; o.y = vy;
                    *(float2*)(outp + (size_t)m * EMB + n) = o;
                }
            }
        }
    }
}

// =============================================================
// tensor-core causal flash attention v2.
// CTA: 128 queries, 256 threads = 8 warps x 16 queries, one (b,h).
// K/V tiles of 64 keys shared by all 8 warps, cp.async double-buffered.
// P -> A-fragment conversion via intra-quad shuffles (no smem round-trip).
// =============================================================
#define KSTRIDE 68
#define VSTRIDE 72
#define KVBUF_K (64 * KSTRIDE)
#define KVBUF_V (64 * VSTRIDE)
#define ATT_SMEM_BYTES ((2 * KVBUF_K + 2 * KVBUF_V) * 4)   // 71680

__global__ __launch_bounds__(256, 2) void attn_mma_kernel()
{
    extern __shared__ uint32_t sm[];
    uint32_t* KsBase = sm;                  // [2][64*KSTRIDE]
    uint32_t* VsBase = sm + 2 * KVBUF_K;    // [2][64*VSTRIDE]
    const int tid  = threadIdx.x;
    const int wid  = tid >> 5;
    const int lane = tid & 31;
    const int g    = lane >> 2;
    const int qd   = lane & 3;

    const int bh = blockIdx.y;
    // reverse x so longest CTAs (largest q0) launch first
    const int q0 = (gridDim.x - 1 - blockIdx.x) * 128;
    const int wq = wid * 16;
    const size_t base = (size_t)bh * SEQ * HSZ;
    const uint32_t* Qp = g_q + base;
    const uint32_t* Kp = g_k + base;
    const uint32_t* Vp = g_v + base;

    const uint32_t sK = (uint32_t)__cvta_generic_to_shared(KsBase);
    const uint32_t sV = (uint32_t)__cvta_generic_to_shared(VsBase);

    const int l_row = tid >> 4;   // 0..15
    const int l_c4  = tid & 15;

    #define ISSUE_TILE(KB, BUF) do { \
        const uint32_t sKb = sK + (BUF) * (KVBUF_K * 4); \
        const uint32_t sVb = sV + (BUF) * (KVBUF_V * 4); \
        _Pragma("unroll") \
        for (int it = 0; it < 4; ++it) { \
            const int row = it * 16 + l_row; \
            cp16(sKb + (row * KSTRIDE + l_c4 * 4) * 4, \
                 Kp + (size_t)((KB) + row) * HSZ + l_c4 * 4); \
            cp16(sVb + (row * VSTRIDE + l_c4 * 4) * 4, \
                 Vp + (size_t)((KB) + row) * HSZ + l_c4 * 4); \
        } \
    } while (0)

    // prefetch tile 0 into buffer 0
    ISSUE_TILE(0, 0);
    cp_commit();

    // ---- stage Q (pre-scaled tf32 bits) through buffer 1 (K rows 0-63, V rows 64-127)
    uint32_t* Kst = KsBase + KVBUF_K;
    uint32_t* Vst = VsBase + KVBUF_V;
    #pragma unroll
    for (int it = 0; it < 8; ++it) {
        const int row = it * 16 + l_row;
        uint4 v = *(const uint4*)(Qp + (size_t)(q0 + row) * HSZ + l_c4 * 4);
        if (row < 64) *(uint4*)&Kst[row * KSTRIDE + l_c4 * 4] = v;
        else          *(uint4*)&Vst[(row - 64) * VSTRIDE + l_c4 * 4] = v;
    }
    __syncthreads();

    uint32_t qf[8][4];
    {
        const uint32_t* qbuf = (wq < 64) ? Kst : Vst;
        const int qs = (wq < 64) ? KSTRIDE : VSTRIDE;
        const int r  = (wq & 63) + g;
        #pragma unroll
        for (int ks = 0; ks < 8; ++ks) {
            qf[ks][0] = qbuf[r * qs + ks * 8 + qd];
            qf[ks][1] = qbuf[(r + 8) * qs + ks * 8 + qd];
            qf[ks][2] = qbuf[r * qs + ks * 8 + qd + 4];
            qf[ks][3] = qbuf[(r + 8) * qs + ks * 8 + qd + 4];
        }
    }
    __syncthreads();   // Q fully consumed before tile 1 overwrites buffer 1

    float of[8][4];
    #pragma unroll
    for (int nt = 0; nt < 8; ++nt)
        #pragma unroll
        for (int c = 0; c < 4; ++c) of[nt][c] = 0.f;
    float m0 = -1e30f, m1 = -1e30f, l0 = 0.f, l1 = 0.f;

    const int ntile = (q0 >> 6) + 2;
    const int row0 = q0 + wq + g;        // this thread's first query row
    for (int kt = 0; kt < ntile; ++kt) {
        const int kb = kt * 64;
        if (kt + 1 < ntile) {
            ISSUE_TILE((kt + 1) * 64, (kt + 1) & 1);
            cp_commit();
        }
        if (kt + 1 < ntile) cp_wait<1>(); else cp_wait<0>();
        __syncthreads();

        // warp-level skip: all of this warp's rows < kb -> tile fully masked
        const bool active = (kb <= q0 + wq + 15);
        if (active) {
            const uint32_t* Ks = KsBase + (kt & 1) * KVBUF_K;
            const uint32_t* Vs = VsBase + (kt & 1) * KVBUF_V;
            const bool need_mask = (kt >= ntile - 2);

            // ---- S = Q K^T ----
            float sf[8][4];
            #pragma unroll
            for (int nt = 0; nt < 8; ++nt) {
                float s4[4] = {0.f, 0.f, 0.f, 0.f};
                #pragma unroll
                for (int ks = 0; ks < 8; ++ks) {
                    uint32_t bf[2];
                    bf[0] = Ks[(nt * 8 + g) * KSTRIDE + ks * 8 + qd];
                    bf[1] = Ks[(nt * 8 + g) * KSTRIDE + ks * 8 + qd + 4];
                    mma_tf32(s4, qf[ks], bf);
                }
                if (need_mask) {
                    const int kl = kb + nt * 8 + 2 * qd;
                    if (kl     > row0)     s4[0] = -1e30f;
                    if (kl + 1 > row0)     s4[1] = -1e30f;
                    if (kl     > row0 + 8) s4[2] = -1e30f;
                    if (kl + 1 > row0 + 8) s4[3] = -1e30f;
                }
                sf[nt][0] = s4[0]; sf[nt][1] = s4[1];
                sf[nt][2] = s4[2]; sf[nt][3] = s4[3];
            }

            // ---- online softmax ----
            float t0 = -1e30f, t1 = -1e30f;
            #pragma unroll
            for (int nt = 0; nt < 8; ++nt) {
                t0 = fmaxf(t0, fmaxf(sf[nt][0], sf[nt][1]));
                t1 = fmaxf(t1, fmaxf(sf[nt][2], sf[nt][3]));
            }
            t0 = fmaxf(t0, __shfl_xor_sync(0xffffffffu, t0, 1));
            t0 = fmaxf(t0, __shfl_xor_sync(0xffffffffu, t0, 2));
            t1 = fmaxf(t1, __shfl_xor_sync(0xffffffffu, t1, 1));
            t1 = fmaxf(t1, __shfl_xor_sync(0xffffffffu, t1, 2));

            const float mn0 = fmaxf(m0, t0);
            const float mn1 = fmaxf(m1, t1);
            const float cr0 = __expf(m0 - mn0);
            const float cr1 = __expf(m1 - mn1);
            m0 = mn0; m1 = mn1;

            float ps0 = 0.f, ps1 = 0.f;
            #pragma unroll
            for (int nt = 0; nt < 8; ++nt) {
                sf[nt][0] = __expf(sf[nt][0] - mn0);
                sf[nt][1] = __expf(sf[nt][1] - mn0);
                sf[nt][2] = __expf(sf[nt][2] - mn1);
                sf[nt][3] = __expf(sf[nt][3] - mn1);
                ps0 += sf[nt][0] + sf[nt][1];
                ps1 += sf[nt][2] + sf[nt][3];
            }
            ps0 += __shfl_xor_sync(0xffffffffu, ps0, 1);
            ps0 += __shfl_xor_sync(0xffffffffu, ps0, 2);
            ps1 += __shfl_xor_sync(0xffffffffu, ps1, 1);
            ps1 += __shfl_xor_sync(0xffffffffu, ps1, 2);
            l0 = l0 * cr0 + ps0;
            l1 = l1 * cr1 + ps1;

            #pragma unroll
            for (int nt = 0; nt < 8; ++nt) {
                of[nt][0] *= cr0; of[nt][1] *= cr0;
                of[nt][2] *= cr1; of[nt][3] *= cr1;
            }

            // ---- O += P V : P acc -> A-frag via intra-quad shuffles ----
            const int L0 = (g << 2) + (qd >> 1);
            #pragma unroll
            for (int ks = 0; ks < 8; ++ks) {
                const uint32_t p0 = f2tf32(sf[ks][0]);
                const uint32_t p1 = f2tf32(sf[ks][1]);
                const uint32_t p2 = f2tf32(sf[ks][2]);
                const uint32_t p3 = f2tf32(sf[ks][3]);
                const uint32_t x0 = __shfl_sync(0xffffffffu, p0, L0);
                const uint32_t x1 = __shfl_sync(0xffffffffu, p1, L0);
                const uint32_t x2 = __shfl_sync(0xffffffffu, p2, L0);
                const uint32_t x3 = __shfl_sync(0xffffffffu, p3, L0);
                const uint32_t y0 = __shfl_sync(0xffffffffu, p0, L0 + 2);
                const uint32_t y1 = __shfl_sync(0xffffffffu, p1, L0 + 2);
                const uint32_t y2 = __shfl_sync(0xffffffffu, p2, L0 + 2);
                const uint32_t y3 = __shfl_sync(0xffffffffu, p3, L0 + 2);
                uint32_t af[4];
                af[0] = (qd & 1) ? x1 : x0;
                af[1] = (qd & 1) ? x3 : x2;
                af[2] = (qd & 1) ? y1 : y0;
                af[3] = (qd & 1) ? y3 : y2;
                #pragma unroll
                for (int nt = 0; nt < 8; ++nt) {
                    uint32_t bf[2];
                    bf[0] = Vs[(ks * 8 + qd) * VSTRIDE + nt * 8 + g];
                    bf[1] = Vs[(ks * 8 + qd + 4) * VSTRIDE + nt * 8 + g];
                    mma_tf32(of[nt], af, bf);
                }
            }
        }
        __syncthreads();
    }
    #undef ISSUE_TILE

    // ---- epilogue: normalize, write y (tf32 bits, [B,T,C]) ----
    const float inv0 = 1.f / l0;
    const float inv1 = 1.f / l1;
    const int b = bh / NHEAD;
    const int h = bh % NHEAD;
    uint32_t* y0 = g_y + ((size_t)b * SEQ + row0) * EMB + h * HSZ;
    uint32_t* y1 = g_y + ((size_t)b * SEQ + row0 + 8) * EMB + h * HSZ;
    #pragma unroll
    for (int nt = 0; nt < 8; ++nt) {
        uint2 o0, o1;
        o0.x = f2tf32(of[nt][0] * inv0); o0.y = f2tf32(of[nt][1] * inv0);
        o1.x = f2tf32(of[nt][2] * inv1); o1.y = f2tf32(of[nt][3] * inv1);
        *(uint2*)(y0 + nt * 8 + 2 * qd) = o0;
        *(uint2*)(y1 + nt * 8 + 2 * qd) = o1;
    }
}

// =============================================================
extern "C" void kernel_launch(void* const* d_in, const int* in_sizes, int n_in,
                              void* d_out, int out_size)
{
    const float* x  = (const float*)d_in[0];
    const float* Wq = (const float*)d_in[1];
    const float* bq = (const float*)d_in[2];
    const float* Wk = (const float*)d_in[3];
    const float* bk = (const float*)d_in[4];
    const float* Wv = (const float*)d_in[5];
    const float* bv = (const float*)d_in[6];
    const float* Wo = (const float*)d_in[7];
    const float* bo = (const float*)d_in[8];
    float* out = (float*)d_out;

    cudaFuncSetAttribute(gemm_kernel<0>, cudaFuncAttributeMaxDynamicSharedMemorySize,
                         GEMM_SMEM_BYTES);
    cudaFuncSetAttribute(gemm_kernel<1>, cudaFuncAttributeMaxDynamicSharedMemorySize,
                         GEMM_SMEM_BYTES);
    cudaFuncSetAttribute(attn_mma_kernel, cudaFuncAttributeMaxDynamicSharedMemorySize,
                         ATT_SMEM_BYTES);

    convert_x_kernel<<<(MTOT * EMB / 4) / 256, 256>>>(x);
    convert_w_kernel<<<dim3((EMB * EMB / 4) / 256, 1, 4), 256>>>(Wq, Wk, Wv, Wo);

    dim3 qkv_grid(EMB / 128, MTOT / 128, 3);
    gemm_kernel<0><<<qkv_grid, 128, GEMM_SMEM_BYTES>>>(bq, bk, bv, nullptr);

    dim3 attn_grid(SEQ / 128, BATCH * NHEAD);   // (16, 64)
    attn_mma_kernel<<<attn_grid, 256, ATT_SMEM_BYTES>>>();

    dim3 oproj_grid(EMB / 128, MTOT / 128);
    gemm_kernel<1><<<oproj_grid, 128, GEMM_SMEM_BYTES>>>(bo, nullptr, nullptr, out);
}

// round 10
// speedup vs baseline: 4.8543x; 1.0654x over previous
#include <cuda_runtime.h>
#include <cuda_bf16.h>
#include <cstdint>
#include <math.h>

// ---------------- problem dims ----------------
#define BATCH 4
#define SEQ   2048
#define EMB   1024
#define NHEAD 16
#define HSZ   64
#define MTOT  (BATCH * SEQ)   // 8192

// ---------------- device scratch (no runtime allocation) ----------------
// All tf32-bit (u32) tensors. q pre-scaled by 1/8.
__device__ __align__(128) uint32_t g_q[(size_t)BATCH * NHEAD * SEQ * HSZ];
__device__ __align__(128) uint32_t g_k[(size_t)BATCH * NHEAD * SEQ * HSZ];
__device__ __align__(128) uint32_t g_v[(size_t)BATCH * NHEAD * SEQ * HSZ];
__device__ __align__(128) uint32_t g_y[(size_t)MTOT * EMB];
__device__ __align__(128) uint32_t g_xt[(size_t)MTOT * EMB];
__device__ __align__(128) uint32_t g_wt[(size_t)4 * EMB * EMB];

// ---------------- helpers ----------------
__device__ __forceinline__ uint32_t f2tf32(float f) {
    uint32_t r;
    asm("cvt.rna.tf32.f32 %0, %1;" : "=r"(r) : "f"(f));
    return r;
}

__device__ __forceinline__ void mma_tf32(float* d, const uint32_t* a, const uint32_t* b) {
    asm volatile(
        "mma.sync.aligned.m16n8k8.row.col.f32.tf32.tf32.f32 "
        "{%0,%1,%2,%3}, {%4,%5,%6,%7}, {%8,%9}, {%0,%1,%2,%3};"
        : "+f"(d[0]), "+f"(d[1]), "+f"(d[2]), "+f"(d[3])
        : "r"(a[0]), "r"(a[1]), "r"(a[2]), "r"(a[3]), "r"(b[0]), "r"(b[1]));
}

__device__ __forceinline__ void cp16(uint32_t sdst, const void* gsrc) {
    asm volatile("cp.async.cg.shared.global [%0], [%1], 16;" :: "r"(sdst), "l"(gsrc));
}
__device__ __forceinline__ void cp_commit() {
    asm volatile("cp.async.commit_group;" ::: "memory");
}
template <int N>
__device__ __forceinline__ void cp_wait() {
    asm volatile("cp.async.wait_group %0;" :: "n"(N) : "memory");
}

// =============================================================
// converters: fp32 -> tf32 bits
// =============================================================
__global__ __launch_bounds__(256) void convert_x_kernel(const float* __restrict__ src)
{
    const size_t i = ((size_t)blockIdx.x * 256 + threadIdx.x) * 4;
    float4 v = *(const float4*)(src + i);
    uint4 t;
    t.x = f2tf32(v.x); t.y = f2tf32(v.y); t.z = f2tf32(v.z); t.w = f2tf32(v.w);
    *(uint4*)(g_xt + i) = t;
}

__global__ __launch_bounds__(256) void convert_w_kernel(
    const float* __restrict__ W0, const float* __restrict__ W1,
    const float* __restrict__ W2, const float* __restrict__ W3)
{
    const int mat = blockIdx.z;
    const float* src = (mat == 0) ? W0 : (mat == 1) ? W1 : (mat == 2) ? W2 : W3;
    uint32_t* dst = g_wt + (size_t)mat * EMB * EMB;
    const size_t i = ((size_t)blockIdx.x * 256 + threadIdx.x) * 4;
    float4 v = *(const float4*)(src + i);
    uint4 t;
    t.x = f2tf32(v.x); t.y = f2tf32(v.y); t.z = f2tf32(v.z); t.w = f2tf32(v.w);
    *(uint4*)(dst + i) = t;
}

// ---------------- GEMM config (unchanged) ----------------
#define APAD 36
#define BPAD 136
#define ABUF (128 * APAD)
#define BBUF (32 * BPAD)
#define GEMM_SMEM_BYTES ((2 * ABUF + 2 * BBUF + 128) * 4)

template <int MODE>
__global__ __launch_bounds__(128) void gemm_kernel(
    const float* __restrict__ bias0, const float* __restrict__ bias1,
    const float* __restrict__ bias2, float* __restrict__ outp)
{
    extern __shared__ uint32_t dynsm[];
    uint32_t* As = dynsm;
    uint32_t* Bs = dynsm + 2 * ABUF;
    float* bias_s = (float*)(dynsm + 2 * ABUF + 2 * BBUF);

    const int tid  = threadIdx.x;
    const int wid  = tid >> 5;
    const int lane = tid & 31;
    const int g    = lane >> 2;
    const int qd   = lane & 3;
    const int wm   = (wid >> 1) * 64;
    const int wn   = (wid & 1) * 64;
    const int n0   = blockIdx.x * 128;
    const int m0   = blockIdx.y * 128;
    const int mat  = (MODE == 0) ? (int)blockIdx.z : 3;

    const uint32_t* A = (MODE == 0) ? g_xt : g_y;
    const uint32_t* W = g_wt + (size_t)mat * EMB * EMB;
    const float* bias = (MODE == 0) ? ((mat == 0) ? bias0 : (mat == 1) ? bias1 : bias2)
                                    : bias0;

    bias_s[tid] = bias[n0 + tid];

    const uint32_t sA = (uint32_t)__cvta_generic_to_shared(As);
    const uint32_t sB = (uint32_t)__cvta_generic_to_shared(Bs);

    const int a_row = tid >> 3;
    const int a_kq  = tid & 7;
    const int b_kr  = tid >> 5;
    const int b_nq  = tid & 31;

    #define ISSUE_CHUNK(K0, BUF) do { \
        const uint32_t sAb = sA + (BUF) * (ABUF * 4); \
        const uint32_t sBb = sB + (BUF) * (BBUF * 4); \
        _Pragma("unroll") \
        for (int it = 0; it < 8; ++it) { \
            const int ar = it * 16 + a_row; \
            cp16(sAb + (ar * APAD + a_kq * 4) * 4, \
                 A + (size_t)(m0 + ar) * EMB + (K0) + a_kq * 4); \
            const int br = it * 4 + b_kr; \
            cp16(sBb + (br * BPAD + b_nq * 4) * 4, \
                 W + (size_t)((K0) + br) * EMB + n0 + b_nq * 4); \
        } \
    } while (0)

    float acc[4][8][4];
    #pragma unroll
    for (int i = 0; i < 4; i++)
        #pragma unroll
        for (int j = 0; j < 8; j++)
            #pragma unroll
            for (int c = 0; c < 4; c++) acc[i][j][c] = 0.f;

    ISSUE_CHUNK(0, 0);
    cp_commit();

    for (int c = 0; c < EMB / 32; ++c) {
        if (c + 1 < EMB / 32) {
            ISSUE_CHUNK((c + 1) * 32, (c + 1) & 1);
            cp_commit();
        }
        if (c + 1 < EMB / 32) cp_wait<1>(); else cp_wait<0>();
        __syncthreads();

        const uint32_t* Ab = As + (c & 1) * ABUF;
        const uint32_t* Bb = Bs + (c & 1) * BBUF;

        #pragma unroll
        for (int ks = 0; ks < 4; ++ks) {
            const int kk = ks * 8 + qd;
            uint32_t af[4][4], bf[8][2];
            #pragma unroll
            for (int mt = 0; mt < 4; ++mt) {
                const int r = wm + mt * 16 + g;
                af[mt][0] = Ab[r * APAD + kk];
                af[mt][1] = Ab[(r + 8) * APAD + kk];
                af[mt][2] = Ab[r * APAD + kk + 4];
                af[mt][3] = Ab[(r + 8) * APAD + kk + 4];
            }
            #pragma unroll
            for (int nt = 0; nt < 8; ++nt) {
                const int n = wn + nt * 8 + g;
                bf[nt][0] = Bb[kk * BPAD + n];
                bf[nt][1] = Bb[(kk + 4) * BPAD + n];
            }
            #pragma unroll
            for (int mt = 0; mt < 4; ++mt)
                #pragma unroll
                for (int nt = 0; nt < 8; ++nt)
                    mma_tf32(acc[mt][nt], af[mt], bf[nt]);
        }
        __syncthreads();
    }
    #undef ISSUE_CHUNK

    #pragma unroll
    for (int mt = 0; mt < 4; ++mt) {
        #pragma unroll
        for (int ci = 0; ci < 2; ++ci) {
            const int m = m0 + wm + mt * 16 + g + ci * 8;
            #pragma unroll
            for (int nt = 0; nt < 8; ++nt) {
                const int nl = wn + nt * 8 + qd * 2;
                const int n  = n0 + nl;
                float vx = acc[mt][nt][ci * 2 + 0] + bias_s[nl];
                float vy = acc[mt][nt][ci * 2 + 1] + bias_s[nl + 1];
                if (MODE == 0) {
                    if (mat == 0) { vx *= 0.125f; vy *= 0.125f; }
                    const int b = m >> 11;
                    const int t = m & (SEQ - 1);
                    const int h = n >> 6;
                    const int d = n & (HSZ - 1);
                    uint32_t* dst = (mat == 0) ? g_q : (mat == 1) ? g_k : g_v;
                    uint2 o;
                    o.x = f2tf32(vx); o.y = f2tf32(vy);
                    *(uint2*)(dst + ((((size_t)b * NHEAD + h) * SEQ) + t) * HSZ + d) = o;
                } else {
                    float2 o; o.x = vx; o.y = vy;
                    *(float2*)(outp + (size_t)m * EMB + n) = o;
                }
            }
        }
    }
}

// =============================================================
// tensor-core causal flash attention v3.
// CTA: 128 queries, 128 threads = 4 warps x 32 queries (2 m16 sub-tiles).
// Each b-fragment load feeds 2 MMAs -> half the LDS per MMA.
// K/V tiles of 64 keys, cp.async double-buffered.
// =============================================================
#define KSTRIDE 68
#define VSTRIDE 72
#define KVBUF_K (64 * KSTRIDE)
#define KVBUF_V (64 * VSTRIDE)
#define ATT_SMEM_BYTES ((2 * KVBUF_K + 2 * KVBUF_V) * 4)   // 71680

__global__ __launch_bounds__(128, 2) void attn_mma_kernel()
{
    extern __shared__ uint32_t sm[];
    uint32_t* KsBase = sm;                  // [2][64*KSTRIDE]
    uint32_t* VsBase = sm + 2 * KVBUF_K;    // [2][64*VSTRIDE]
    const int tid  = threadIdx.x;
    const int wid  = tid >> 5;
    const int lane = tid & 31;
    const int g    = lane >> 2;
    const int qd   = lane & 3;

    const int bh = blockIdx.y;
    const int q0 = (gridDim.x - 1 - blockIdx.x) * 128;   // longest first
    const int wq = wid * 32;
    const size_t base = (size_t)bh * SEQ * HSZ;
    const uint32_t* Qp = g_q + base;
    const uint32_t* Kp = g_k + base;
    const uint32_t* Vp = g_v + base;

    const uint32_t sK = (uint32_t)__cvta_generic_to_shared(KsBase);
    const uint32_t sV = (uint32_t)__cvta_generic_to_shared(VsBase);

    const int l_row = tid >> 4;   // 0..7
    const int l_c4  = tid & 15;

    #define ISSUE_TILE(KB, BUF) do { \
        const uint32_t sKb = sK + (BUF) * (KVBUF_K * 4); \
        const uint32_t sVb = sV + (BUF) * (KVBUF_V * 4); \
        _Pragma("unroll") \
        for (int it = 0; it < 8; ++it) { \
            const int row = it * 8 + l_row; \
            cp16(sKb + (row * KSTRIDE + l_c4 * 4) * 4, \
                 Kp + (size_t)((KB) + row) * HSZ + l_c4 * 4); \
            cp16(sVb + (row * VSTRIDE + l_c4 * 4) * 4, \
                 Vp + (size_t)((KB) + row) * HSZ + l_c4 * 4); \
        } \
    } while (0)

    ISSUE_TILE(0, 0);
    cp_commit();

    // ---- stage Q through buffer 1 (rows 0-63 -> Kst, 64-127 -> Vst) ----
    uint32_t* Kst = KsBase + KVBUF_K;
    uint32_t* Vst = VsBase + KVBUF_V;
    #pragma unroll
    for (int it = 0; it < 16; ++it) {
        const int row = it * 8 + l_row;
        uint4 v = *(const uint4*)(Qp + (size_t)(q0 + row) * HSZ + l_c4 * 4);
        if (row < 64) *(uint4*)&Kst[row * KSTRIDE + l_c4 * 4] = v;
        else          *(uint4*)&Vst[(row - 64) * VSTRIDE + l_c4 * 4] = v;
    }
    __syncthreads();

    // ---- Q fragments: 2 m16 sub-tiles per warp ----
    uint32_t qf[2][8][4];
    {
        const uint32_t* qbuf = (wq < 64) ? Kst : Vst;
        const int qs = (wq < 64) ? KSTRIDE : VSTRIDE;
        #pragma unroll
        for (int mt = 0; mt < 2; ++mt) {
            const int r = (wq & 63) + mt * 16 + g;
            #pragma unroll
            for (int ks = 0; ks < 8; ++ks) {
                qf[mt][ks][0] = qbuf[r * qs + ks * 8 + qd];
                qf[mt][ks][1] = qbuf[(r + 8) * qs + ks * 8 + qd];
                qf[mt][ks][2] = qbuf[r * qs + ks * 8 + qd + 4];
                qf[mt][ks][3] = qbuf[(r + 8) * qs + ks * 8 + qd + 4];
            }
        }
    }
    __syncthreads();   // Q consumed before tile 1 overwrites buffer 1

    float of[2][8][4];
    #pragma unroll
    for (int mt = 0; mt < 2; ++mt)
        #pragma unroll
        for (int nt = 0; nt < 8; ++nt)
            #pragma unroll
            for (int c = 0; c < 4; ++c) of[mt][nt][c] = 0.f;
    float mx[4] = {-1e30f, -1e30f, -1e30f, -1e30f};   // [mt*2 + half]
    float li[4] = {0.f, 0.f, 0.f, 0.f};

    const int ntile = (q0 >> 6) + 2;
    const int wrow = q0 + wq;                 // warp's first query row
    const int L0 = (g << 2) + (qd >> 1);      // shuffle source lane
    for (int kt = 0; kt < ntile; ++kt) {
        const int kb = kt * 64;
        if (kt + 1 < ntile) {
            ISSUE_TILE((kt + 1) * 64, (kt + 1) & 1);
            cp_commit();
        }
        if (kt + 1 < ntile) cp_wait<1>(); else cp_wait<0>();
        __syncthreads();

        const bool active = (kb <= wrow + 31);
        if (active) {
            const uint32_t* Ks = KsBase + (kt & 1) * KVBUF_K;
            const uint32_t* Vs = VsBase + (kt & 1) * KVBUF_V;
            const bool need_mask = (kb + 63 > wrow);

            // ---- S = Q K^T (both m-tiles share b-fragments) ----
            float sf[2][8][4];
            #pragma unroll
            for (int nt = 0; nt < 8; ++nt) {
                float s0[4] = {0.f, 0.f, 0.f, 0.f};
                float s1[4] = {0.f, 0.f, 0.f, 0.f};
                #pragma unroll
                for (int ks = 0; ks < 8; ++ks) {
                    uint32_t bf[2];
                    bf[0] = Ks[(nt * 8 + g) * KSTRIDE + ks * 8 + qd];
                    bf[1] = Ks[(nt * 8 + g) * KSTRIDE + ks * 8 + qd + 4];
                    mma_tf32(s0, qf[0][ks], bf);
                    mma_tf32(s1, qf[1][ks], bf);
                }
                if (need_mask) {
                    const int kl = kb + nt * 8 + 2 * qd;
                    const int r0 = wrow + g;
                    if (kl     > r0)      s0[0] = -1e30f;
                    if (kl + 1 > r0)      s0[1] = -1e30f;
                    if (kl     > r0 + 8)  s0[2] = -1e30f;
                    if (kl + 1 > r0 + 8)  s0[3] = -1e30f;
                    if (kl     > r0 + 16) s1[0] = -1e30f;
                    if (kl + 1 > r0 + 16) s1[1] = -1e30f;
                    if (kl     > r0 + 24) s1[2] = -1e30f;
                    if (kl + 1 > r0 + 24) s1[3] = -1e30f;
                }
                #pragma unroll
                for (int c = 0; c < 4; ++c) { sf[0][nt][c] = s0[c]; sf[1][nt][c] = s1[c]; }
            }

            // ---- online softmax (per m-tile, per half) ----
            #pragma unroll
            for (int mt = 0; mt < 2; ++mt) {
                float t0 = -1e30f, t1 = -1e30f;
                #pragma unroll
                for (int nt = 0; nt < 8; ++nt) {
                    t0 = fmaxf(t0, fmaxf(sf[mt][nt][0], sf[mt][nt][1]));
                    t1 = fmaxf(t1, fmaxf(sf[mt][nt][2], sf[mt][nt][3]));
                }
                t0 = fmaxf(t0, __shfl_xor_sync(0xffffffffu, t0, 1));
                t0 = fmaxf(t0, __shfl_xor_sync(0xffffffffu, t0, 2));
                t1 = fmaxf(t1, __shfl_xor_sync(0xffffffffu, t1, 1));
                t1 = fmaxf(t1, __shfl_xor_sync(0xffffffffu, t1, 2));

                const float mn0 = fmaxf(mx[mt * 2 + 0], t0);
                const float mn1 = fmaxf(mx[mt * 2 + 1], t1);
                const float cr0 = __expf(mx[mt * 2 + 0] - mn0);
                const float cr1 = __expf(mx[mt * 2 + 1] - mn1);
                mx[mt * 2 + 0] = mn0;
                mx[mt * 2 + 1] = mn1;

                float ps0 = 0.f, ps1 = 0.f;
                #pragma unroll
                for (int nt = 0; nt < 8; ++nt) {
                    sf[mt][nt][0] = __expf(sf[mt][nt][0] - mn0);
                    sf[mt][nt][1] = __expf(sf[mt][nt][1] - mn0);
                    sf[mt][nt][2] = __expf(sf[mt][nt][2] - mn1);
                    sf[mt][nt][3] = __expf(sf[mt][nt][3] - mn1);
                    ps0 += sf[mt][nt][0] + sf[mt][nt][1];
                    ps1 += sf[mt][nt][2] + sf[mt][nt][3];
                }
                ps0 += __shfl_xor_sync(0xffffffffu, ps0, 1);
                ps0 += __shfl_xor_sync(0xffffffffu, ps0, 2);
                ps1 += __shfl_xor_sync(0xffffffffu, ps1, 1);
                ps1 += __shfl_xor_sync(0xffffffffu, ps1, 2);
                li[mt * 2 + 0] = li[mt * 2 + 0] * cr0 + ps0;
                li[mt * 2 + 1] = li[mt * 2 + 1] * cr1 + ps1;

                #pragma unroll
                for (int nt = 0; nt < 8; ++nt) {
                    of[mt][nt][0] *= cr0; of[mt][nt][1] *= cr0;
                    of[mt][nt][2] *= cr1; of[mt][nt][3] *= cr1;
                }
            }

            // ---- O += P V (shared V b-frags; P via intra-quad shuffles) ----
            #pragma unroll
            for (int ks = 0; ks < 8; ++ks) {
                uint32_t af0[4], af1[4];
                #pragma unroll
                for (int mt = 0; mt < 2; ++mt) {
                    const uint32_t p0 = f2tf32(sf[mt][ks][0]);
                    const uint32_t p1 = f2tf32(sf[mt][ks][1]);
                    const uint32_t p2 = f2tf32(sf[mt][ks][2]);
                    const uint32_t p3 = f2tf32(sf[mt][ks][3]);
                    const uint32_t x0 = __shfl_sync(0xffffffffu, p0, L0);
                    const uint32_t x1 = __shfl_sync(0xffffffffu, p1, L0);
                    const uint32_t x2 = __shfl_sync(0xffffffffu, p2, L0);
                    const uint32_t x3 = __shfl_sync(0xffffffffu, p3, L0);
                    const uint32_t y0 = __shfl_sync(0xffffffffu, p0, L0 + 2);
                    const uint32_t y1 = __shfl_sync(0xffffffffu, p1, L0 + 2);
                    const uint32_t y2 = __shfl_sync(0xffffffffu, p2, L0 + 2);
                    const uint32_t y3 = __shfl_sync(0xffffffffu, p3, L0 + 2);
                    uint32_t* af = (mt == 0) ? af0 : af1;
                    af[0] = (qd & 1) ? x1 : x0;
                    af[1] = (qd & 1) ? x3 : x2;
                    af[2] = (qd & 1) ? y1 : y0;
                    af[3] = (qd & 1) ? y3 : y2;
                }
                #pragma unroll
                for (int nt = 0; nt < 8; ++nt) {
                    uint32_t bf[2];
                    bf[0] = Vs[(ks * 8 + qd) * VSTRIDE + nt * 8 + g];
                    bf[1] = Vs[(ks * 8 + qd + 4) * VSTRIDE + nt * 8 + g];
                    mma_tf32(of[0][nt], af0, bf);
                    mma_tf32(of[1][nt], af1, bf);
                }
            }
        }
        __syncthreads();
    }
    #undef ISSUE_TILE

    // ---- epilogue: normalize, write y (tf32 bits, [B,T,C]) ----
    const int b = bh / NHEAD;
    const int h = bh % NHEAD;
    #pragma unroll
    for (int mt = 0; mt < 2; ++mt) {
        const float inv0 = 1.f / li[mt * 2 + 0];
        const float inv1 = 1.f / li[mt * 2 + 1];
        const int r0 = wrow + mt * 16 + g;
        uint32_t* y0 = g_y + ((size_t)b * SEQ + r0) * EMB + h * HSZ;
        uint32_t* y1 = g_y + ((size_t)b * SEQ + r0 + 8) * EMB + h * HSZ;
        #pragma unroll
        for (int nt = 0; nt < 8; ++nt) {
            uint2 o0, o1;
            o0.x = f2tf32(of[mt][nt][0] * inv0); o0.y = f2tf32(of[mt][nt][1] * inv0);
            o1.x = f2tf32(of[mt][nt][2] * inv1); o1.y = f2tf32(of[mt][nt][3] * inv1);
            *(uint2*)(y0 + nt * 8 + 2 * qd) = o0;
            *(uint2*)(y1 + nt * 8 + 2 * qd) = o1;
        }
    }
}

// =============================================================
extern "C" void kernel_launch(void* const* d_in, const int* in_sizes, int n_in,
                              void* d_out, int out_size)
{
    const float* x  = (const float*)d_in[0];
    const float* Wq = (const float*)d_in[1];
    const float* bq = (const float*)d_in[2];
    const float* Wk = (const float*)d_in[3];
    const float* bk = (const float*)d_in[4];
    const float* Wv = (const float*)d_in[5];
    const float* bv = (const float*)d_in[6];
    const float* Wo = (const float*)d_in[7];
    const float* bo = (const float*)d_in[8];
    float* out = (float*)d_out;

    cudaFuncSetAttribute(gemm_kernel<0>, cudaFuncAttributeMaxDynamicSharedMemorySize,
                         GEMM_SMEM_BYTES);
    cudaFuncSetAttribute(gemm_kernel<1>, cudaFuncAttributeMaxDynamicSharedMemorySize,
                         GEMM_SMEM_BYTES);
    cudaFuncSetAttribute(attn_mma_kernel, cudaFuncAttributeMaxDynamicSharedMemorySize,
                         ATT_SMEM_BYTES);

    convert_x_kernel<<<(MTOT * EMB / 4) / 256, 256>>>(x);
    convert_w_kernel<<<dim3((EMB * EMB / 4) / 256, 1, 4), 256>>>(Wq, Wk, Wv, Wo);

    dim3 qkv_grid(EMB / 128, MTOT / 128, 3);
    gemm_kernel<0><<<qkv_grid, 128, GEMM_SMEM_BYTES>>>(bq, bk, bv, nullptr);

    dim3 attn_grid(SEQ / 128, BATCH * NHEAD);   // (16, 64)
    attn_mma_kernel<<<attn_grid, 128, ATT_SMEM_BYTES>>>();

    dim3 oproj_grid(EMB / 128, MTOT / 128);
    gemm_kernel<1><<<oproj_grid, 128, GEMM_SMEM_BYTES>>>(bo, nullptr, nullptr, out);
}